// round 14
// baseline (speedup 1.0000x reference)
#include <cuda_runtime.h>
#include <math.h>
#include <float.h>

#define JAX_PARTITIONABLE 1

#define BB     16
#define TENC   256
#define TDEC   200
#define NMELS  80
#define PREN   256
#define ENCD   512
#define DECD   1024
#define ARNND  1024
#define ADIMD  128
#define NFILTD 32
#define KCONV  31
#define PADC   15
#define NBLK   148

typedef unsigned long long ull;

// ------------------- scratch (device globals; no allocation) ----------------
__device__ float g_y1[(TDEC + 1) * BB * PREN];
__device__ float g_dec_ins[(TDEC + 1) * BB * PREN];
__device__ float g_pmem[BB * TENC * ADIMD];
__device__ float g_ah[2][BB * ARNND];
__device__ float g_ac[BB * ARNND];
__device__ float g_dh[2][BB * DECD];
__device__ float g_dc[BB * DECD];
__device__ float g_aw[BB * TENC];
__device__ float g_awc[BB * TENC];
__device__ float g_actx[BB * ENCD];
__device__ float g_q[BB * ADIMD];
__device__ float g_energy[BB * TENC];
__device__ float g_convf[BB * TENC * NFILTD];

__device__ unsigned g_bar_cnt = 0;
__device__ unsigned g_bar_epoch = 0;

// ----------------------------- grid barrier ---------------------------------
__device__ __forceinline__ void gsync() {
    __syncthreads();
    if (threadIdx.x == 0) {
        volatile unsigned* ep = &g_bar_epoch;
        unsigned e = *ep;
        __threadfence();
        unsigned old = atomicAdd(&g_bar_cnt, 1u);
        if (old == (unsigned)(NBLK - 1)) {
            g_bar_cnt = 0;
            __threadfence();
            *ep = e + 1u;
        } else {
            while (*ep == e) { __nanosleep(32); }
            __threadfence();
        }
    }
    __syncthreads();
}

// ------------------------------ packed f32x2 fma ----------------------------
__device__ __forceinline__ ull ffma2(ull a, ull b, ull c) {
    ull d;
    asm("fma.rn.f32x2 %0, %1, %2, %3;" : "=l"(d) : "l"(a), "l"(b), "l"(c));
    return d;
}
__device__ __forceinline__ float2 u2f(ull v) {
    float2 f;
    asm("mov.b64 {%0, %1}, %2;" : "=f"(f.x), "=f"(f.y) : "l"(v));
    return f;
}

// ------------------------------- threefry ----------------------------------
__host__ __device__ inline void threefry2x32(unsigned k0, unsigned k1,
                                             unsigned x0, unsigned x1,
                                             unsigned& o0, unsigned& o1) {
    unsigned ks2 = k0 ^ k1 ^ 0x1BD11BDAu;
    x0 += k0; x1 += k1;
#define TFR(d) { x0 += x1; x1 = (x1 << (d)) | (x1 >> (32 - (d))); x1 ^= x0; }
    TFR(13) TFR(15) TFR(26) TFR(6)
    x0 += k1;  x1 += ks2 + 1u;
    TFR(17) TFR(29) TFR(16) TFR(24)
    x0 += ks2; x1 += k0 + 2u;
    TFR(13) TFR(15) TFR(26) TFR(6)
    x0 += k0;  x1 += k1 + 3u;
    TFR(17) TFR(29) TFR(16) TFR(24)
    x0 += k1;  x1 += ks2 + 4u;
    TFR(13) TFR(15) TFR(26) TFR(6)
    x0 += ks2; x1 += k0 + 5u;
#undef TFR
    o0 = x0; o1 = x1;
}

__device__ inline bool drop_keep(unsigned k0, unsigned k1, unsigned i) {
#if JAX_PARTITIONABLE
    unsigned o0, o1;
    threefry2x32(k0, k1, 0u, i, o0, o1);
    unsigned bits = o0 ^ o1;
#else
    const unsigned half = ((TDEC + 1) * BB * PREN) / 2u;
    unsigned lo = (i < half) ? i : (i - half);
    unsigned o0, o1;
    threefry2x32(k0, k1, lo, lo + half, o0, o1);
    unsigned bits = (i < half) ? o0 : o1;
#endif
    return (bits >> 31) == 0u;
}

// ------------------------------ prologue ------------------------------------
__global__ void init_kernel() {
    int i = blockIdx.x * blockDim.x + threadIdx.x;
    if (i < BB * ARNND) { g_ah[0][i] = 0.f; g_ac[i] = 0.f; g_dh[0][i] = 0.f; g_dc[i] = 0.f; }
    if (i < BB * TENC)  { g_aw[i] = 0.f; g_awc[i] = 0.f; }
    if (i < BB * ENCD)  { g_actx[i] = 0.f; }
}

__global__ void prenet1_kernel(const float* __restrict__ dec_inputs,
                               const float* __restrict__ w1,
                               unsigned k0, unsigned k1) {
    __shared__ float xr[NMELS];
    int t = blockIdx.x / BB, b = blockIdx.x % BB;
    int j = threadIdx.x;
    if (j < NMELS) xr[j] = (t == 0) ? 0.f : dec_inputs[(b * NMELS + j) * TDEC + (t - 1)];
    __syncthreads();
    float acc = 0.f;
    const float* w = w1 + j * NMELS;
    #pragma unroll
    for (int m = 0; m < NMELS; m++) acc += xr[m] * w[m];
    acc = fmaxf(acc, 0.f);
    unsigned flat = blockIdx.x * PREN + j;
    g_y1[flat] = drop_keep(k0, k1, flat) ? 2.f * acc : 0.f;
}

__global__ void prenet2_kernel(const float* __restrict__ w2,
                               unsigned k0, unsigned k1) {
    __shared__ float xr[PREN];
    int j = threadIdx.x;
    xr[j] = g_y1[blockIdx.x * PREN + j];
    __syncthreads();
    float acc = 0.f;
    const float4* w = (const float4*)(w2 + (size_t)j * PREN);
    const float4* xs = (const float4*)xr;
    #pragma unroll 8
    for (int m = 0; m < PREN / 4; m++) {
        float4 wv = w[m]; float4 xv = xs[m];
        acc += wv.x * xv.x + wv.y * xv.y + wv.z * xv.z + wv.w * xv.w;
    }
    acc = fmaxf(acc, 0.f);
    unsigned flat = blockIdx.x * PREN + j;
    g_dec_ins[flat] = drop_keep(k0, k1, flat) ? 2.f * acc : 0.f;
}

__global__ void pmem_kernel(const float* __restrict__ memory,
                            const float* __restrict__ memory_w) {
    __shared__ float ms[ENCD];
    int t = blockIdx.x, b = blockIdx.y, tid = threadIdx.x;
    const float* mrow = memory + ((size_t)(b * TENC) + t) * ENCD;
    for (int i = tid; i < ENCD; i += 128) ms[i] = mrow[i];
    __syncthreads();
    float acc = 0.f;
    const float4* w = (const float4*)(memory_w + (size_t)tid * ENCD);
    const float4* xs = (const float4*)ms;
    #pragma unroll 8
    for (int k = 0; k < ENCD / 4; k++) {
        float4 wv = w[k]; float4 xv = xs[k];
        acc += wv.x * xv.x + wv.y * xv.y + wv.z * xv.z + wv.w * xv.w;
    }
    g_pmem[((size_t)(b * TENC) + t) * ADIMD + tid] = acc;
}

// ---------------------------- megakernel phases -----------------------------

// blocks 0..127; 32 rows/block; 8 threads/row; 2 batches/thread; packed f32x2 over k
__device__ void lstm_phase(char* sraw, int which, int parity, int t,
                           const float* __restrict__ w_ih,
                           const float* __restrict__ w_hh,
                           const float* __restrict__ bias) {
    float* xs = (float*)sraw;                 // [16][66]
    float* sg = xs + 16 * 66;                 // [32][16]
    const float *in1, *hin; float *hout, *cst; int in1dim;
    if (which == 0) {
        in1 = g_dec_ins + (size_t)t * BB * PREN; in1dim = PREN;
        hin = g_ah[parity]; hout = g_ah[parity ^ 1]; cst = g_ac;
    } else {
        in1 = g_ah[parity ^ 1]; in1dim = ARNND;
        hin = g_dh[parity]; hout = g_dh[parity ^ 1]; cst = g_dc;
    }
    const float* in2 = g_actx;
    const int indim = in1dim + ENCD;          // 768 or 1536
    const int Ktot = indim + 1024;            // 1792 or 2560
    int tid = threadIdx.x;
    int rr = tid >> 3, bg = tid & 7;
    int gate = rr >> 3, cell = rr & 7;
    int row = (gate << 10) + (blockIdx.x << 3) + cell;
    int b0 = bg << 1;
    int sb = tid >> 4;                        // staging batch
    int skq = (tid & 15) << 2;                // staging k-offset

    ull accA0 = 0ull, accA1 = 0ull, accB0 = 0ull, accB1 = 0ull;

    for (int k0 = 0; k0 < Ktot; k0 += 64) {
        int k = k0 + skq;
        float4 v;
        if (k < in1dim)      v = *(const float4*)(in1 + (size_t)sb * in1dim + k);
        else if (k < indim)  v = *(const float4*)(in2 + (size_t)sb * ENCD + (k - in1dim));
        else                 v = *(const float4*)(hin + (size_t)sb * 1024 + (k - indim));
        float* dst = xs + sb * 66 + skq;
        *(float2*)(dst)     = make_float2(v.x, v.y);
        *(float2*)(dst + 2) = make_float2(v.z, v.w);
        __syncthreads();
        const float* w = (k0 < indim) ? (w_ih + (size_t)row * indim + k0)
                                      : (w_hh + (size_t)row * 1024 + (k0 - indim));
        const float* xA = xs + b0 * 66;
        const float* xB = xA + 66;
        #pragma unroll
        for (int kk = 0; kk < 64; kk += 4) {
            ulonglong2 wv = *(const ulonglong2*)(w + kk);
            accA0 = ffma2(wv.x, *(const ull*)(xA + kk),     accA0);
            accA1 = ffma2(wv.y, *(const ull*)(xA + kk + 2), accA1);
            accB0 = ffma2(wv.x, *(const ull*)(xB + kk),     accB0);
            accB1 = ffma2(wv.y, *(const ull*)(xB + kk + 2), accB1);
        }
        __syncthreads();
    }
    float2 a0 = u2f(accA0), a1 = u2f(accA1);
    float2 c0 = u2f(accB0), c1 = u2f(accB1);
    float bb = bias[row];
    sg[rr * 16 + b0]     = a0.x + a0.y + a1.x + a1.y + bb;
    sg[rr * 16 + b0 + 1] = c0.x + c0.y + c1.x + c1.y + bb;
    __syncthreads();
    if (tid < 128) {
        int cl2 = tid >> 4, b2 = tid & 15;
        float gi = sg[cl2 * 16 + b2];
        float gf = sg[(8 + cl2) * 16 + b2];
        float gg = sg[(16 + cl2) * 16 + b2];
        float go = sg[(24 + cl2) * 16 + b2];
        int ci = b2 * 1024 + (blockIdx.x << 3) + cl2;
        float cold = cst[ci];
        float si = 1.f / (1.f + expf(-gi));
        float sf = 1.f / (1.f + expf(-gf));
        float so = 1.f / (1.f + expf(-go));
        float cn = sf * cold + si * tanhf(gg);
        cst[ci] = cn;
        hout[ci] = so * tanhf(cn);
    }
}

// blocks 128..147 : mel projection for step tprev (20 blocks, 1280 outputs)
__device__ void proj_phase(int bid2, int parity, int tprev,
                           const float* __restrict__ proj_w,
                           const float* __restrict__ proj_b,
                           float* __restrict__ out) {
    int tid = threadIdx.x;
    int o = bid2 * 64 + (tid >> 2);           // 0..1279
    int q4 = tid & 3;
    int b = o / NMELS, mel = o - b * NMELS;
    const float* dh = g_dh[parity] + (size_t)b * DECD;
    const float* ax = g_actx + (size_t)b * ENCD;
    const float* w = proj_w + (size_t)mel * (DECD + ENCD);
    ull acc = 0ull;
    int kst = q4 * 384, ken = kst + 384;
    for (int k = kst; k < ken; k += 2) {
        ull wv = *(const ull*)(w + k);
        ull xv = (k < DECD) ? *(const ull*)(dh + k) : *(const ull*)(ax + (k - DECD));
        acc = ffma2(wv, xv, acc);
    }
    float2 f = u2f(acc);
    float s = f.x + f.y;
    s += __shfl_down_sync(0xffffffffu, s, 2, 4);
    s += __shfl_down_sync(0xffffffffu, s, 1, 4);
    if (q4 == 0)
        out[(size_t)b * (NMELS * TDEC) + mel * TDEC + tprev] = s + proj_b[mel];
}

// blocks 0..15 : q[b] = query_w @ ah
__device__ void query_phase(char* sraw, int b, int parity,
                            const float* __restrict__ query_w) {
    float* sh = (float*)sraw;                 // 1024
    int tid = threadIdx.x;
    const float* ah = g_ah[parity ^ 1] + (size_t)b * ARNND;
    for (int i = tid; i < ARNND; i += 256) sh[i] = ah[i];
    __syncthreads();
    if (tid < ADIMD) {
        const float* w = query_w + (size_t)tid * ARNND;
        ull a0 = 0ull, a1 = 0ull;
        for (int k = 0; k < ARNND; k += 4) {
            ulonglong2 wv = *(const ulonglong2*)(w + k);
            a0 = ffma2(wv.x, *(const ull*)(sh + k), a0);
            a1 = ffma2(wv.y, *(const ull*)(sh + k + 2), a1);
        }
        float2 f0 = u2f(a0), f1 = u2f(a1);
        g_q[b * ADIMD + tid] = f0.x + f0.y + f1.x + f1.y;
    }
}

// blocks 16..143 : location conv -> g_convf[b][t][32]; task=(b, tchunk of 32 t)
__device__ void conv_phase(char* sraw, int task,
                           const float* __restrict__ loc_conv_w) {
    float* ws0 = (float*)sraw;                // 62 (+pad)
    float* ws1 = ws0 + 64;
    float* cw  = ws1 + 64;                    // 64*31
    int b = task >> 3, tc = task & 7;
    int tid = threadIdx.x;
    int t0 = tc * 32 - PADC;
    for (int i = tid; i < 62; i += 256) {
        int tt = t0 + i;
        bool ok = (tt >= 0 && tt < TENC);
        ws0[i] = ok ? g_aw[b * TENC + tt] : 0.f;
        ws1[i] = ok ? g_awc[b * TENC + tt] : 0.f;
    }
    for (int i = tid; i < 64 * KCONV; i += 256) cw[i] = loc_conv_w[i];
    __syncthreads();
    int c = tid & 31, tl0 = tid >> 5;
    const float* w0 = cw + (c * 2) * KCONV;
    const float* w1 = w0 + KCONV;
    #pragma unroll
    for (int j = 0; j < 4; j++) {
        int tl = tl0 + j * 8;
        float s = 0.f;
        #pragma unroll
        for (int tap = 0; tap < KCONV; tap++)
            s += ws0[tl + tap] * w0[tap] + ws1[tl + tap] * w1[tap];
        g_convf[((b << 8) + tc * 32 + tl) * NFILTD + c] = s;
    }
}

// all blocks : energies for all 4096 (b,t) pairs, one warp per pair
__device__ void energy_phase(char* sraw,
                             const float* __restrict__ loc_dense_w,
                             const float* __restrict__ v_w) {
    float* ldt = (float*)sraw;                // [32][128] transposed
    float* sv  = ldt + 4096;                  // 128
    int tid = threadIdx.x;
    for (int i = tid; i < ADIMD * NFILTD; i += 256) {
        int a = i >> 5, c = i & 31;
        ldt[c * ADIMD + a] = loc_dense_w[i];
    }
    if (tid < ADIMD) sv[tid] = v_w[tid];
    __syncthreads();
    int lane = tid & 31, wid = tid >> 5;
    for (int p = blockIdx.x * 8 + wid; p < BB * TENC; p += NBLK * 8) {
        int b = p >> 8;
        float myconv = g_convf[p * NFILTD + lane];
        const float* qb = g_q + b * ADIMD;
        const float* pm = g_pmem + (size_t)p * ADIMD;
        float s0 = qb[lane]      + pm[lane];
        float s1 = qb[32 + lane] + pm[32 + lane];
        float s2 = qb[64 + lane] + pm[64 + lane];
        float s3 = qb[96 + lane] + pm[96 + lane];
        #pragma unroll
        for (int c = 0; c < NFILTD; c++) {
            float fc = __shfl_sync(0xffffffffu, myconv, c);
            const float* lr = ldt + c * ADIMD;
            s0 += lr[lane] * fc;
            s1 += lr[32 + lane] * fc;
            s2 += lr[64 + lane] * fc;
            s3 += lr[96 + lane] * fc;
        }
        float e = tanhf(fminf(fmaxf(s0, -20.f), 20.f)) * sv[lane]
                + tanhf(fminf(fmaxf(s1, -20.f), 20.f)) * sv[32 + lane]
                + tanhf(fminf(fmaxf(s2, -20.f), 20.f)) * sv[64 + lane]
                + tanhf(fminf(fmaxf(s3, -20.f), 20.f)) * sv[96 + lane];
        #pragma unroll
        for (int o = 16; o > 0; o >>= 1) e += __shfl_down_sync(0xffffffffu, e, o);
        if (lane == 0) g_energy[p] = e;
    }
}

// blocks 0..127 : softmax (+aw/awc by ec==0) and context chunk
__device__ void ctx_phase(char* sraw, int bid,
                          const int* __restrict__ lengths,
                          const float* __restrict__ memory) {
    float* red = (float*)sraw;                // 256
    float* saw = red + 256;                   // 256
    int b = bid >> 3, ec = bid & 7;
    int tid = threadIdx.x;
    int len = lengths[b];
    bool masked = (tid < len);                // reference masks the PREFIX
    float e = masked ? -FLT_MAX : g_energy[b * TENC + tid];
    red[tid] = e; __syncthreads();
    for (int s = 128; s > 0; s >>= 1) { if (tid < s) red[tid] = fmaxf(red[tid], red[tid + s]); __syncthreads(); }
    float m = red[0]; __syncthreads();
    float ex = masked ? 0.f : expf(e - m);
    red[tid] = ex; __syncthreads();
    for (int s = 128; s > 0; s >>= 1) { if (tid < s) red[tid] += red[tid + s]; __syncthreads(); }
    float aw = ex / red[0];
    saw[tid] = aw;
    if (ec == 0) {
        g_aw[b * TENC + tid] = aw;
        g_awc[b * TENC + tid] += aw;
    }
    __syncthreads();
    int e0 = (ec << 6) + (tid & 63), tq = tid >> 6;
    const float* mem = memory + (size_t)b * TENC * ENCD;
    float acc = 0.f;
    int ts = tq * 64;
    #pragma unroll 8
    for (int tt = ts; tt < ts + 64; tt++)
        acc += saw[tt] * mem[(size_t)tt * ENCD + e0];
    red[tid] = acc; __syncthreads();
    if (tid < 64)
        g_actx[b * ENCD + (ec << 6) + tid] =
            red[tid] + red[tid + 64] + red[tid + 128] + red[tid + 192];
}

// ------------------------------- megakernel ---------------------------------
__global__ __launch_bounds__(256, 1)
void mega_kernel(const float* __restrict__ memory,
                 const int* __restrict__ lengths,
                 const float* __restrict__ attn_w_ih,
                 const float* __restrict__ attn_w_hh,
                 const float* __restrict__ attn_b,
                 const float* __restrict__ dec_w_ih,
                 const float* __restrict__ dec_w_hh,
                 const float* __restrict__ dec_b,
                 const float* __restrict__ proj_w,
                 const float* __restrict__ proj_b,
                 const float* __restrict__ query_w,
                 const float* __restrict__ v_w,
                 const float* __restrict__ loc_conv_w,
                 const float* __restrict__ loc_dense_w,
                 float* __restrict__ out) {
    __shared__ __align__(16) char sraw[17536];
    const int bid = blockIdx.x;
    for (int t = 0; t <= TDEC; t++) {
        const int parity = t & 1;
        // Phase A: attn LSTM (blocks 0..127) + projection of step t-1 (128..147)
        if (bid < 128) {
            if (t < TDEC) lstm_phase(sraw, 0, parity, t, attn_w_ih, attn_w_hh, attn_b);
        } else if (t > 0) {
            proj_phase(bid - 128, parity, t - 1, proj_w, proj_b, out);
        }
        gsync();
        if (t == TDEC) break;
        // Phase B1: query (0..15) + location conv (16..143)
        if (bid < 16) query_phase(sraw, bid, parity, query_w);
        else if (bid < 144) conv_phase(sraw, bid - 16, loc_conv_w);
        gsync();
        // Phase B2: energies
        energy_phase(sraw, loc_dense_w, v_w);
        gsync();
        // Phase B3: softmax + context
        if (bid < 128) ctx_phase(sraw, bid, lengths, memory);
        gsync();
        // Phase C: decoder LSTM
        if (bid < 128) lstm_phase(sraw, 1, parity, t, dec_w_ih, dec_w_hh, dec_b);
        gsync();
    }
}

// --------------------------------- host -------------------------------------
extern "C" void kernel_launch(void* const* d_in, const int* in_sizes, int n_in,
                              void* d_out, int out_size) {
    (void)in_sizes; (void)n_in; (void)out_size;
    const float* memory     = (const float*)d_in[0];
    const float* dec_inputs = (const float*)d_in[1];
    const int*   lengths    = (const int*)d_in[2];
    const float* prenet_w1  = (const float*)d_in[3];
    const float* prenet_w2  = (const float*)d_in[4];
    const float* attn_w_ih  = (const float*)d_in[5];
    const float* attn_w_hh  = (const float*)d_in[6];
    const float* attn_b     = (const float*)d_in[7];
    const float* dec_w_ih   = (const float*)d_in[8];
    const float* dec_w_hh   = (const float*)d_in[9];
    const float* dec_b      = (const float*)d_in[10];
    const float* proj_w     = (const float*)d_in[11];
    const float* proj_b     = (const float*)d_in[12];
    const float* query_w    = (const float*)d_in[13];
    const float* memory_w   = (const float*)d_in[14];
    const float* v_w        = (const float*)d_in[15];
    const float* loc_conv_w = (const float*)d_in[16];
    const float* loc_dense_w= (const float*)d_in[17];
    float* out = (float*)d_out;

    unsigned dk0_0, dk0_1, dk1_0, dk1_1;
#if JAX_PARTITIONABLE
    threefry2x32(0u, 42u, 0u, 0u, dk0_0, dk0_1);
    threefry2x32(0u, 42u, 0u, 1u, dk1_0, dk1_1);
#else
    unsigned a0, a1, b0, b1;
    threefry2x32(0u, 42u, 0u, 2u, a0, a1);
    threefry2x32(0u, 42u, 1u, 3u, b0, b1);
    dk0_0 = a0; dk0_1 = b0; dk1_0 = a1; dk1_1 = b1;
#endif

    init_kernel<<<64, 256>>>();
    prenet1_kernel<<<(TDEC + 1) * BB, 256>>>(dec_inputs, prenet_w1, dk0_0, dk0_1);
    prenet2_kernel<<<(TDEC + 1) * BB, 256>>>(prenet_w2, dk1_0, dk1_1);
    pmem_kernel<<<dim3(TENC, BB), 128>>>(memory, memory_w);
    mega_kernel<<<NBLK, 256>>>(memory, lengths,
                               attn_w_ih, attn_w_hh, attn_b,
                               dec_w_ih, dec_w_hh, dec_b,
                               proj_w, proj_b, query_w, v_w,
                               loc_conv_w, loc_dense_w, out);
}

// round 15
// speedup vs baseline: 1.0377x; 1.0377x over previous
#include <cuda_runtime.h>
#include <math.h>
#include <float.h>

#define JAX_PARTITIONABLE 1

#define BB     16
#define TENC   256
#define TDEC   200
#define NMELS  80
#define PREN   256
#define ENCD   512
#define DECD   1024
#define ARNND  1024
#define ADIMD  128
#define NFILTD 32
#define KCONV  31
#define PADC   15
#define NBLK   148
#define NTHR   512

typedef unsigned long long ull;

// ------------------- scratch (device globals; no allocation) ----------------
__device__ float g_y1[(TDEC + 1) * BB * PREN];
__device__ float g_dec_ins[(TDEC + 1) * BB * PREN];
__device__ float g_pmem[BB * TENC * ADIMD];
__device__ float g_ah[2][BB * ARNND];
__device__ float g_ac[BB * ARNND];
__device__ float g_dh[2][BB * DECD];
__device__ float g_dc[BB * DECD];
__device__ float g_aw[BB * TENC];
__device__ float g_awc[BB * TENC];
__device__ float g_actx[BB * ENCD];
__device__ float g_energy[BB * TENC];

__device__ unsigned g_bar_cnt = 0;
__device__ unsigned g_bar_epoch = 0;

// ----------------------------- grid barrier ---------------------------------
__device__ __forceinline__ void gsync() {
    __syncthreads();
    if (threadIdx.x == 0) {
        volatile unsigned* ep = &g_bar_epoch;
        unsigned e = *ep;
        __threadfence();
        unsigned old = atomicAdd(&g_bar_cnt, 1u);
        if (old == (unsigned)(NBLK - 1)) {
            g_bar_cnt = 0;
            __threadfence();
            *ep = e + 1u;
        } else {
            while (*ep == e) { __nanosleep(20); }
            __threadfence();
        }
    }
    __syncthreads();
}

// ------------------------------ packed f32x2 fma ----------------------------
__device__ __forceinline__ ull ffma2(ull a, ull b, ull c) {
    ull d;
    asm("fma.rn.f32x2 %0, %1, %2, %3;" : "=l"(d) : "l"(a), "l"(b), "l"(c));
    return d;
}
__device__ __forceinline__ float2 u2f(ull v) {
    float2 f;
    asm("mov.b64 {%0, %1}, %2;" : "=f"(f.x), "=f"(f.y) : "l"(v));
    return f;
}

// ----------------------------- L1-bypassing loads ---------------------------
__device__ __forceinline__ float4 ldcg4(const float* p) {
    float4 v;
    asm volatile("ld.global.cg.v4.f32 {%0,%1,%2,%3}, [%4];"
                 : "=f"(v.x), "=f"(v.y), "=f"(v.z), "=f"(v.w) : "l"(p));
    return v;
}
__device__ __forceinline__ float2 ldcg2(const float* p) {
    float2 v;
    asm volatile("ld.global.cg.v2.f32 {%0,%1}, [%2];"
                 : "=f"(v.x), "=f"(v.y) : "l"(p));
    return v;
}
__device__ __forceinline__ ull ldcg2u(const float* p) {
    ull v;
    asm volatile("ld.global.cg.b64 %0, [%1];" : "=l"(v) : "l"(p));
    return v;
}
__device__ __forceinline__ float ldcg1(const float* p) {
    float v;
    asm volatile("ld.global.cg.f32 %0, [%1];" : "=f"(v) : "l"(p));
    return v;
}

// ------------------------------- threefry ----------------------------------
__host__ __device__ inline void threefry2x32(unsigned k0, unsigned k1,
                                             unsigned x0, unsigned x1,
                                             unsigned& o0, unsigned& o1) {
    unsigned ks2 = k0 ^ k1 ^ 0x1BD11BDAu;
    x0 += k0; x1 += k1;
#define TFR(d) { x0 += x1; x1 = (x1 << (d)) | (x1 >> (32 - (d))); x1 ^= x0; }
    TFR(13) TFR(15) TFR(26) TFR(6)
    x0 += k1;  x1 += ks2 + 1u;
    TFR(17) TFR(29) TFR(16) TFR(24)
    x0 += ks2; x1 += k0 + 2u;
    TFR(13) TFR(15) TFR(26) TFR(6)
    x0 += k0;  x1 += k1 + 3u;
    TFR(17) TFR(29) TFR(16) TFR(24)
    x0 += k1;  x1 += ks2 + 4u;
    TFR(13) TFR(15) TFR(26) TFR(6)
    x0 += ks2; x1 += k0 + 5u;
#undef TFR
    o0 = x0; o1 = x1;
}

__device__ inline bool drop_keep(unsigned k0, unsigned k1, unsigned i) {
#if JAX_PARTITIONABLE
    unsigned o0, o1;
    threefry2x32(k0, k1, 0u, i, o0, o1);
    unsigned bits = o0 ^ o1;
#else
    const unsigned half = ((TDEC + 1) * BB * PREN) / 2u;
    unsigned lo = (i < half) ? i : (i - half);
    unsigned o0, o1;
    threefry2x32(k0, k1, lo, lo + half, o0, o1);
    unsigned bits = (i < half) ? o0 : o1;
#endif
    return (bits >> 31) == 0u;
}

// ------------------------------ prologue ------------------------------------
__global__ void init_kernel() {
    int i = blockIdx.x * blockDim.x + threadIdx.x;
    if (i < BB * ARNND) { g_ah[0][i] = 0.f; g_ac[i] = 0.f; g_dh[0][i] = 0.f; g_dc[i] = 0.f; }
    if (i < BB * TENC)  { g_aw[i] = 0.f; g_awc[i] = 0.f; }
    if (i < BB * ENCD)  { g_actx[i] = 0.f; }
}

__global__ void prenet1_kernel(const float* __restrict__ dec_inputs,
                               const float* __restrict__ w1,
                               unsigned k0, unsigned k1) {
    __shared__ float xr[NMELS];
    int t = blockIdx.x / BB, b = blockIdx.x % BB;
    int j = threadIdx.x;
    if (j < NMELS) xr[j] = (t == 0) ? 0.f : dec_inputs[(b * NMELS + j) * TDEC + (t - 1)];
    __syncthreads();
    float acc = 0.f;
    const float* w = w1 + j * NMELS;
    #pragma unroll
    for (int m = 0; m < NMELS; m++) acc += xr[m] * w[m];
    acc = fmaxf(acc, 0.f);
    unsigned flat = blockIdx.x * PREN + j;
    g_y1[flat] = drop_keep(k0, k1, flat) ? 2.f * acc : 0.f;
}

__global__ void prenet2_kernel(const float* __restrict__ w2,
                               unsigned k0, unsigned k1) {
    __shared__ float xr[PREN];
    int j = threadIdx.x;
    xr[j] = g_y1[blockIdx.x * PREN + j];
    __syncthreads();
    float acc = 0.f;
    const float4* w = (const float4*)(w2 + (size_t)j * PREN);
    const float4* xs = (const float4*)xr;
    #pragma unroll 8
    for (int m = 0; m < PREN / 4; m++) {
        float4 wv = w[m]; float4 xv = xs[m];
        acc += wv.x * xv.x + wv.y * xv.y + wv.z * xv.z + wv.w * xv.w;
    }
    acc = fmaxf(acc, 0.f);
    unsigned flat = blockIdx.x * PREN + j;
    g_dec_ins[flat] = drop_keep(k0, k1, flat) ? 2.f * acc : 0.f;
}

// pmem v2: grid (8 tchunks, 16 b), block 256; tiles through smem.
__global__ void pmem_kernel(const float* __restrict__ memory,
                            const float* __restrict__ memory_w) {
    __shared__ float ms[32][64];
    __shared__ float ws[128][66];
    int tc = blockIdx.x, b = blockIdx.y, tid = threadIdx.x;
    int a = tid & 127, tg = tid >> 7;
    ull acc[16];
    #pragma unroll
    for (int i = 0; i < 16; i++) acc[i] = 0ull;
    for (int k0 = 0; k0 < ENCD; k0 += 64) {
        for (int i4 = tid; i4 < 512; i4 += 256) {
            int t = i4 >> 4, kq = (i4 & 15) << 2;
            float4 v = *(const float4*)(memory + ((size_t)(b * TENC) + tc * 32 + t) * ENCD + k0 + kq);
            ms[t][kq] = v.x; ms[t][kq + 1] = v.y; ms[t][kq + 2] = v.z; ms[t][kq + 3] = v.w;
        }
        for (int i4 = tid; i4 < 2048; i4 += 256) {
            int aa = i4 >> 4, kq = (i4 & 15) << 2;
            float4 v = *(const float4*)(memory_w + (size_t)aa * ENCD + k0 + kq);
            float* d = &ws[aa][kq];
            d[0] = v.x; d[1] = v.y; d[2] = v.z; d[3] = v.w;
        }
        __syncthreads();
        #pragma unroll 4
        for (int kp = 0; kp < 64; kp += 2) {
            ull wv = *(const ull*)&ws[a][kp];
            #pragma unroll
            for (int i = 0; i < 16; i++)
                acc[i] = ffma2(wv, *(const ull*)&ms[tg * 16 + i][kp], acc[i]);
        }
        __syncthreads();
    }
    #pragma unroll
    for (int i = 0; i < 16; i++) {
        float2 f = u2f(acc[i]);
        g_pmem[((size_t)(b * TENC) + tc * 32 + tg * 16 + i) * ADIMD + a] = f.x + f.y;
    }
}

// ---------------------------- megakernel phases -----------------------------

// blocks 0..127; 32 rows/block; 512 thr: 1 row x 1 batch each; full-x smem staging.
__device__ void lstm_phase(float* smem_f, int which, int parity, int t,
                           const float* __restrict__ w_ih,
                           const float* __restrict__ w_hh,
                           const float* __restrict__ bias) {
    const float *in1, *hin; float *hout, *cst; int in1dim;
    if (which == 0) {
        in1 = g_dec_ins + (size_t)t * BB * PREN; in1dim = PREN;
        hin = g_ah[parity]; hout = g_ah[parity ^ 1]; cst = g_ac;
    } else {
        in1 = g_ah[parity ^ 1]; in1dim = ARNND;
        hin = g_dh[parity]; hout = g_dh[parity ^ 1]; cst = g_dc;
    }
    const float* in2 = g_actx;
    const int indim = in1dim + ENCD;          // 768 or 1536
    const int Ktot = indim + 1024;            // 1792 or 2560
    const int Kpad = Ktot + 2;                // ≡ 2 (mod 32): conflict-free
    float* xs = smem_f;                       // [16][Kpad]
    float* sg = xs + 16 * Kpad;               // [32][16]
    int tid = threadIdx.x;

    // ---- stage all of x = [in1 | actx | hin] for all 16 batches, once ----
    const int quads = Ktot >> 2;              // quads per batch
    for (int i4 = tid; i4 < 16 * quads; i4 += NTHR) {
        int b = i4 / quads;
        int k = (i4 - b * quads) << 2;
        float4 v;
        if (k < in1dim)      v = ldcg4(in1 + (size_t)b * in1dim + k);
        else if (k < indim)  v = ldcg4(in2 + (size_t)b * ENCD + (k - in1dim));
        else                 v = ldcg4(hin + (size_t)b * 1024 + (k - indim));
        float* dst = xs + b * Kpad + k;
        *(float2*)dst       = make_float2(v.x, v.y);
        *(float2*)(dst + 2) = make_float2(v.z, v.w);
    }
    __syncthreads();

    // ---- GEMM: no further syncs; scoreboard overlaps everything ----
    int rr = tid >> 4, bg = tid & 15;
    int gate = rr >> 3, cell = rr & 7;
    int row = (gate << 10) + (blockIdx.x << 3) + cell;
    const float* xb = xs + bg * Kpad;
    ull a0 = 0ull, a1 = 0ull;
    const float* w1r = w_ih + (size_t)row * indim;
    #pragma unroll 8
    for (int k = 0; k < indim; k += 4) {
        ulonglong2 wv = *(const ulonglong2*)(w1r + k);
        a0 = ffma2(wv.x, *(const ull*)(xb + k),     a0);
        a1 = ffma2(wv.y, *(const ull*)(xb + k + 2), a1);
    }
    const float* w2r = w_hh + (size_t)row * 1024;
    const float* xh = xb + indim;
    #pragma unroll 8
    for (int k = 0; k < 1024; k += 4) {
        ulonglong2 wv = *(const ulonglong2*)(w2r + k);
        a0 = ffma2(wv.x, *(const ull*)(xh + k),     a0);
        a1 = ffma2(wv.y, *(const ull*)(xh + k + 2), a1);
    }
    float2 f0 = u2f(a0), f1 = u2f(a1);
    sg[rr * 16 + bg] = f0.x + f0.y + f1.x + f1.y + bias[row];
    __syncthreads();

    if (tid < 128) {
        int cl2 = tid >> 4, b2 = tid & 15;
        float gi = sg[cl2 * 16 + b2];
        float gf = sg[(8 + cl2) * 16 + b2];
        float gg = sg[(16 + cl2) * 16 + b2];
        float go = sg[(24 + cl2) * 16 + b2];
        int ci = b2 * 1024 + (blockIdx.x << 3) + cl2;
        float cold = cst[ci];
        float si = 1.f / (1.f + expf(-gi));
        float sf = 1.f / (1.f + expf(-gf));
        float so = 1.f / (1.f + expf(-go));
        float cn = sf * cold + si * tanhf(gg);
        cst[ci] = cn;
        hout[ci] = so * tanhf(cn);
    }
}

// blocks 128..147: projection for step tprev (1280 outputs, 64/block, 8 thr each)
__device__ void proj_phase(int bid2, int parity, int tprev,
                           const float* __restrict__ proj_w,
                           const float* __restrict__ proj_b,
                           float* __restrict__ out) {
    int tid = threadIdx.x;
    int o = bid2 * 64 + (tid >> 3);
    int q8 = tid & 7;
    int b = o / NMELS, mel = o - b * NMELS;
    const float* dh = g_dh[parity] + (size_t)b * DECD;
    const float* ax = g_actx + (size_t)b * ENCD;
    const float* w = proj_w + (size_t)mel * (DECD + ENCD);
    ull acc = 0ull;
    int kst = q8 * 192;
    #pragma unroll 8
    for (int k = kst; k < kst + 192; k += 2) {
        ull wv = *(const ull*)(w + k);
        ull xv = (k < DECD) ? ldcg2u(dh + k) : ldcg2u(ax + (k - DECD));
        acc = ffma2(wv, xv, acc);
    }
    float2 f = u2f(acc);
    float s = f.x + f.y;
    s += __shfl_down_sync(0xffffffffu, s, 4, 8);
    s += __shfl_down_sync(0xffffffffu, s, 2, 8);
    s += __shfl_down_sync(0xffffffffu, s, 1, 8);
    if (q8 == 0)
        out[(size_t)b * (NMELS * TDEC) + mel * TDEC + tprev] = s + proj_b[mel];
}

// blocks 0..127: fused query (redundant per block) + conv + energy.
// block = (b = bid>>3, tc = bid&7 -> 32 t's)
__device__ void energy_fused_phase(float* smem_f, int bid, int parity,
                                   const float* __restrict__ query_w,
                                   const float* __restrict__ loc_conv_w,
                                   const float* __restrict__ loc_dense_w,
                                   const float* __restrict__ v_w) {
    float* sh_ah  = smem_f;          // 1024
    float* sh_q   = sh_ah + 1024;    // 128
    float* sh_ws0 = sh_q + 128;      // 64 (62 used)
    float* sh_ws1 = sh_ws0 + 64;     // 64
    float* sh_cw  = sh_ws1 + 64;     // 1984
    float* sh_cv  = sh_cw + 1984;    // 32*33
    float* sh_ldt = sh_cv + 1056;    // 32*130
    float* sh_v   = sh_ldt + 4160;   // 128
    int b = bid >> 3, tc = bid & 7;
    int tid = threadIdx.x;

    // ---- stage everything ----
    {
        float2 v = ldcg2(g_ah[parity ^ 1] + (size_t)b * ARNND + tid * 2);
        sh_ah[tid * 2] = v.x; sh_ah[tid * 2 + 1] = v.y;
    }
    if (tid < 62) {
        int tt = tc * 32 - PADC + tid;
        bool ok = (tt >= 0 && tt < TENC);
        sh_ws0[tid] = ok ? ldcg1(g_aw + b * TENC + tt) : 0.f;
        sh_ws1[tid] = ok ? ldcg1(g_awc + b * TENC + tt) : 0.f;
    }
    for (int i = tid; i < 64 * KCONV; i += NTHR) sh_cw[i] = loc_conv_w[i];
    for (int i = tid; i < ADIMD * NFILTD; i += NTHR) {
        int a = i >> 5, c = i & 31;
        sh_ldt[c * 130 + a] = loc_dense_w[i];
    }
    if (tid < ADIMD) sh_v[tid] = v_w[tid];
    __syncthreads();

    // ---- q[b] = query_w @ ah (4 threads per output) ----
    {
        int a = tid >> 2, kq = tid & 3;
        const float* w = query_w + (size_t)a * ARNND + kq * 256;
        const float* x = sh_ah + kq * 256;
        ull a0 = 0ull, a1 = 0ull;
        #pragma unroll 8
        for (int k = 0; k < 256; k += 4) {
            ulonglong2 wv = *(const ulonglong2*)(w + k);
            a0 = ffma2(wv.x, *(const ull*)(x + k),     a0);
            a1 = ffma2(wv.y, *(const ull*)(x + k + 2), a1);
        }
        float2 f0 = u2f(a0), f1 = u2f(a1);
        float s = f0.x + f0.y + f1.x + f1.y;
        s += __shfl_down_sync(0xffffffffu, s, 2, 4);
        s += __shfl_down_sync(0xffffffffu, s, 1, 4);
        if (kq == 0) sh_q[a] = s;
    }
    // ---- conv: 32 t x 32 filters ----
    for (int i = tid; i < 1024; i += NTHR) {
        int tl = i >> 5, c = i & 31;
        const float* w0 = sh_cw + c * 62;
        float s = 0.f;
        #pragma unroll
        for (int tap = 0; tap < KCONV; tap++)
            s += sh_ws0[tl + tap] * w0[tap] + sh_ws1[tl + tap] * w0[KCONV + tap];
        sh_cv[tl * 33 + c] = s;
    }
    __syncthreads();

    // ---- energy: 16 warps x 2 t each ----
    int wid = tid >> 5, lane = tid & 31;
    #pragma unroll
    for (int j = 0; j < 2; j++) {
        int tl = wid * 2 + j;
        int t = tc * 32 + tl;
        const float* pm = g_pmem + ((size_t)(b * TENC) + t) * ADIMD;
        float s0 = sh_q[lane]      + pm[lane];
        float s1 = sh_q[lane + 32] + pm[lane + 32];
        float s2 = sh_q[lane + 64] + pm[lane + 64];
        float s3 = sh_q[lane + 96] + pm[lane + 96];
        #pragma unroll
        for (int c = 0; c < NFILTD; c++) {
            float fc = sh_cv[tl * 33 + c];
            const float* lr = sh_ldt + c * 130;
            s0 += lr[lane] * fc;
            s1 += lr[lane + 32] * fc;
            s2 += lr[lane + 64] * fc;
            s3 += lr[lane + 96] * fc;
        }
        float e = tanhf(fminf(fmaxf(s0, -20.f), 20.f)) * sh_v[lane]
                + tanhf(fminf(fmaxf(s1, -20.f), 20.f)) * sh_v[lane + 32]
                + tanhf(fminf(fmaxf(s2, -20.f), 20.f)) * sh_v[lane + 64]
                + tanhf(fminf(fmaxf(s3, -20.f), 20.f)) * sh_v[lane + 96];
        #pragma unroll
        for (int o = 16; o > 0; o >>= 1) e += __shfl_down_sync(0xffffffffu, e, o);
        if (lane == 0) g_energy[b * TENC + t] = e;
    }
}

// blocks 0..127: softmax (+aw/awc update by ec==0) and 64-wide context chunk
__device__ void ctx_phase(float* smem_f, int bid,
                          const int* __restrict__ lengths,
                          const float* __restrict__ memory) {
    float* red  = smem_f;            // 256
    float* saw  = red + 256;         // 256
    float* part = saw + 256;         // 512
    int b = bid >> 3, ec = bid & 7;
    int tid = threadIdx.x;
    int len = lengths[b];
    float e = 0.f, ex = 0.f;
    bool masked = true;
    if (tid < 256) {
        masked = (tid < len);                   // reference masks the PREFIX
        e = masked ? -FLT_MAX : ldcg1(g_energy + b * TENC + tid);
        red[tid] = e;
    }
    __syncthreads();
    for (int s = 128; s > 0; s >>= 1) {
        if (tid < s) red[tid] = fmaxf(red[tid], red[tid + s]);
        __syncthreads();
    }
    float m = red[0];
    __syncthreads();
    if (tid < 256) {
        ex = masked ? 0.f : expf(e - m);
        red[tid] = ex;
    }
    __syncthreads();
    for (int s = 128; s > 0; s >>= 1) {
        if (tid < s) red[tid] += red[tid + s];
        __syncthreads();
    }
    float inv = 1.f / red[0];
    if (tid < 256) {
        float aw = ex * inv;
        saw[tid] = aw;
        if (ec == 0) {
            g_aw[b * TENC + tid] = aw;
            g_awc[b * TENC + tid] += aw;
        }
    }
    __syncthreads();
    // context: 8 t-groups x 64 e-lanes
    int e0 = (ec << 6) + (tid & 63), tq = tid >> 6;
    const float* mem = memory + (size_t)b * TENC * ENCD;
    float acc = 0.f;
    int ts = tq * 32;
    #pragma unroll 8
    for (int tt = ts; tt < ts + 32; tt++)
        acc += saw[tt] * mem[(size_t)tt * ENCD + e0];
    part[tid] = acc;
    __syncthreads();
    if (tid < 64) {
        float s = 0.f;
        #pragma unroll
        for (int q = 0; q < 8; q++) s += part[q * 64 + tid];
        g_actx[b * ENCD + (ec << 6) + tid] = s;
    }
}

// ------------------------------- megakernel ---------------------------------
__global__ __launch_bounds__(NTHR, 1)
void mega_kernel(const float* __restrict__ memory,
                 const int* __restrict__ lengths,
                 const float* __restrict__ attn_w_ih,
                 const float* __restrict__ attn_w_hh,
                 const float* __restrict__ attn_b,
                 const float* __restrict__ dec_w_ih,
                 const float* __restrict__ dec_w_hh,
                 const float* __restrict__ dec_b,
                 const float* __restrict__ proj_w,
                 const float* __restrict__ proj_b,
                 const float* __restrict__ query_w,
                 const float* __restrict__ v_w,
                 const float* __restrict__ loc_conv_w,
                 const float* __restrict__ loc_dense_w,
                 float* __restrict__ out) {
    extern __shared__ __align__(16) float smem_f[];
    const int bid = blockIdx.x;
    for (int t = 0; t < TDEC; t++) {
        const int parity = t & 1;
        // A: attn LSTM (0..127) + proj of step t-1 (128..147)
        if (bid < 128) lstm_phase(smem_f, 0, parity, t, attn_w_ih, attn_w_hh, attn_b);
        else if (t > 0) proj_phase(bid - 128, parity, t - 1, proj_w, proj_b, out);
        gsync();
        // B: query + conv + energy (0..127)
        if (bid < 128) energy_fused_phase(smem_f, bid, parity, query_w,
                                          loc_conv_w, loc_dense_w, v_w);
        gsync();
        // C: softmax + context (0..127)
        if (bid < 128) ctx_phase(smem_f, bid, lengths, memory);
        gsync();
        // D: decoder LSTM (0..127)
        if (bid < 128) lstm_phase(smem_f, 1, parity, t, dec_w_ih, dec_w_hh, dec_b);
        gsync();
    }
    // final projection for t = TDEC-1 (parity of "step TDEC" = 0)
    if (bid >= 128) proj_phase(bid - 128, TDEC & 1, TDEC - 1, proj_w, proj_b, out);
}

// --------------------------------- host -------------------------------------
extern "C" void kernel_launch(void* const* d_in, const int* in_sizes, int n_in,
                              void* d_out, int out_size) {
    (void)in_sizes; (void)n_in; (void)out_size;
    const float* memory     = (const float*)d_in[0];
    const float* dec_inputs = (const float*)d_in[1];
    const int*   lengths    = (const int*)d_in[2];
    const float* prenet_w1  = (const float*)d_in[3];
    const float* prenet_w2  = (const float*)d_in[4];
    const float* attn_w_ih  = (const float*)d_in[5];
    const float* attn_w_hh  = (const float*)d_in[6];
    const float* attn_b     = (const float*)d_in[7];
    const float* dec_w_ih   = (const float*)d_in[8];
    const float* dec_w_hh   = (const float*)d_in[9];
    const float* dec_b      = (const float*)d_in[10];
    const float* proj_w     = (const float*)d_in[11];
    const float* proj_b     = (const float*)d_in[12];
    const float* query_w    = (const float*)d_in[13];
    const float* memory_w   = (const float*)d_in[14];
    const float* v_w        = (const float*)d_in[15];
    const float* loc_conv_w = (const float*)d_in[16];
    const float* loc_dense_w= (const float*)d_in[17];
    float* out = (float*)d_out;

    unsigned dk0_0, dk0_1, dk1_0, dk1_1;
#if JAX_PARTITIONABLE
    threefry2x32(0u, 42u, 0u, 0u, dk0_0, dk0_1);
    threefry2x32(0u, 42u, 0u, 1u, dk1_0, dk1_1);
#else
    unsigned a0, a1, b0, b1;
    threefry2x32(0u, 42u, 0u, 2u, a0, a1);
    threefry2x32(0u, 42u, 1u, 3u, b0, b1);
    dk0_0 = a0; dk0_1 = b0; dk1_0 = a1; dk1_1 = b1;
#endif

    // dec LSTM x-staging: 16 * (2560+2) floats + 512 gate floats
    const int SMEM_MEGA = (16 * (2560 + 2) + 512) * (int)sizeof(float);
    static int configured = 0;
    if (!configured) {
        cudaFuncSetAttribute(mega_kernel,
                             cudaFuncAttributeMaxDynamicSharedMemorySize, SMEM_MEGA);
        configured = 1;
    }

    init_kernel<<<64, 256>>>();
    prenet1_kernel<<<(TDEC + 1) * BB, 256>>>(dec_inputs, prenet_w1, dk0_0, dk0_1);
    prenet2_kernel<<<(TDEC + 1) * BB, 256>>>(prenet_w2, dk1_0, dk1_1);
    pmem_kernel<<<dim3(8, BB), 256>>>(memory, memory_w);
    mega_kernel<<<NBLK, NTHR, SMEM_MEGA>>>(memory, lengths,
                                           attn_w_ih, attn_w_hh, attn_b,
                                           dec_w_ih, dec_w_hh, dec_b,
                                           proj_w, proj_b, query_w, v_w,
                                           loc_conv_w, loc_dense_w, out);
}

// round 16
// speedup vs baseline: 1.4697x; 1.4162x over previous
#include <cuda_runtime.h>
#include <math.h>
#include <float.h>

#define JAX_PARTITIONABLE 1

#define BB     16
#define TENC   256
#define TDEC   200
#define NMELS  80
#define PREN   256
#define ENCD   512
#define DECD   1024
#define ARNND  1024
#define ADIMD  128
#define NFILTD 32
#define KCONV  31
#define PADC   15
#define NBLK   148
#define NTHR   512

typedef unsigned long long ull;

// ------------------- scratch (device globals; no allocation) ----------------
__device__ float g_y1[(TDEC + 1) * BB * PREN];
__device__ float g_dec_ins[(TDEC + 1) * BB * PREN];
__device__ float g_pmem[BB * TENC * ADIMD];
__device__ float g_ah[2][BB * ARNND];
__device__ float g_ac[BB * ARNND];
__device__ float g_dh[2][BB * DECD];
__device__ float g_dc[BB * DECD];
__device__ float g_aw[BB * TENC];
__device__ float g_awc[BB * TENC];
__device__ float g_actx[BB * ENCD];
__device__ float g_q[BB * ADIMD];
__device__ float g_energy[BB * TENC];
__device__ float g_convf[BB * TENC * NFILTD];

__device__ unsigned g_bar_cnt = 0;
__device__ unsigned g_bar_epoch = 0;

// ----------------------------- grid barrier ---------------------------------
__device__ __forceinline__ void gsync() {
    __syncthreads();
    if (threadIdx.x == 0) {
        volatile unsigned* ep = &g_bar_epoch;
        unsigned e = *ep;
        __threadfence();
        unsigned old = atomicAdd(&g_bar_cnt, 1u);
        if (old == (unsigned)(NBLK - 1)) {
            g_bar_cnt = 0;
            __threadfence();
            *ep = e + 1u;
        } else {
            while (*ep == e) { __nanosleep(20); }
            __threadfence();
        }
    }
    __syncthreads();
}

// ------------------------------ packed f32x2 fma ----------------------------
__device__ __forceinline__ ull ffma2(ull a, ull b, ull c) {
    ull d;
    asm("fma.rn.f32x2 %0, %1, %2, %3;" : "=l"(d) : "l"(a), "l"(b), "l"(c));
    return d;
}
__device__ __forceinline__ float2 u2f(ull v) {
    float2 f;
    asm("mov.b64 {%0, %1}, %2;" : "=f"(f.x), "=f"(f.y) : "l"(v));
    return f;
}

// ----------------------------- L1-bypassing loads ---------------------------
__device__ __forceinline__ float4 ldcg4(const float* p) {
    float4 v;
    asm volatile("ld.global.cg.v4.f32 {%0,%1,%2,%3}, [%4];"
                 : "=f"(v.x), "=f"(v.y), "=f"(v.z), "=f"(v.w) : "l"(p));
    return v;
}
__device__ __forceinline__ ull ldcg2u(const float* p) {
    ull v;
    asm volatile("ld.global.cg.b64 %0, [%1];" : "=l"(v) : "l"(p));
    return v;
}
__device__ __forceinline__ float ldcg1(const float* p) {
    float v;
    asm volatile("ld.global.cg.f32 %0, [%1];" : "=f"(v) : "l"(p));
    return v;
}

// ------------------------------- threefry ----------------------------------
__host__ __device__ inline void threefry2x32(unsigned k0, unsigned k1,
                                             unsigned x0, unsigned x1,
                                             unsigned& o0, unsigned& o1) {
    unsigned ks2 = k0 ^ k1 ^ 0x1BD11BDAu;
    x0 += k0; x1 += k1;
#define TFR(d) { x0 += x1; x1 = (x1 << (d)) | (x1 >> (32 - (d))); x1 ^= x0; }
    TFR(13) TFR(15) TFR(26) TFR(6)
    x0 += k1;  x1 += ks2 + 1u;
    TFR(17) TFR(29) TFR(16) TFR(24)
    x0 += ks2; x1 += k0 + 2u;
    TFR(13) TFR(15) TFR(26) TFR(6)
    x0 += k0;  x1 += k1 + 3u;
    TFR(17) TFR(29) TFR(16) TFR(24)
    x0 += k1;  x1 += ks2 + 4u;
    TFR(13) TFR(15) TFR(26) TFR(6)
    x0 += ks2; x1 += k0 + 5u;
#undef TFR
    o0 = x0; o1 = x1;
}

__device__ inline bool drop_keep(unsigned k0, unsigned k1, unsigned i) {
#if JAX_PARTITIONABLE
    unsigned o0, o1;
    threefry2x32(k0, k1, 0u, i, o0, o1);
    unsigned bits = o0 ^ o1;
#else
    const unsigned half = ((TDEC + 1) * BB * PREN) / 2u;
    unsigned lo = (i < half) ? i : (i - half);
    unsigned o0, o1;
    threefry2x32(k0, k1, lo, lo + half, o0, o1);
    unsigned bits = (i < half) ? o0 : o1;
#endif
    return (bits >> 31) == 0u;
}

// ------------------------------ prologue ------------------------------------
__global__ void init_kernel() {
    int i = blockIdx.x * blockDim.x + threadIdx.x;
    if (i < BB * ARNND) { g_ah[0][i] = 0.f; g_ac[i] = 0.f; g_dh[0][i] = 0.f; g_dc[i] = 0.f; }
    if (i < BB * TENC)  { g_aw[i] = 0.f; g_awc[i] = 0.f; }
    if (i < BB * ENCD)  { g_actx[i] = 0.f; }
}

__global__ void prenet1_kernel(const float* __restrict__ dec_inputs,
                               const float* __restrict__ w1,
                               unsigned k0, unsigned k1) {
    __shared__ float xr[NMELS];
    int t = blockIdx.x / BB, b = blockIdx.x % BB;
    int j = threadIdx.x;
    if (j < NMELS) xr[j] = (t == 0) ? 0.f : dec_inputs[(b * NMELS + j) * TDEC + (t - 1)];
    __syncthreads();
    float acc = 0.f;
    const float* w = w1 + j * NMELS;
    #pragma unroll
    for (int m = 0; m < NMELS; m++) acc += xr[m] * w[m];
    acc = fmaxf(acc, 0.f);
    unsigned flat = blockIdx.x * PREN + j;
    g_y1[flat] = drop_keep(k0, k1, flat) ? 2.f * acc : 0.f;
}

__global__ void prenet2_kernel(const float* __restrict__ w2,
                               unsigned k0, unsigned k1) {
    __shared__ float xr[PREN];
    int j = threadIdx.x;
    xr[j] = g_y1[blockIdx.x * PREN + j];
    __syncthreads();
    float acc = 0.f;
    const float4* w = (const float4*)(w2 + (size_t)j * PREN);
    const float4* xs = (const float4*)xr;
    #pragma unroll 8
    for (int m = 0; m < PREN / 4; m++) {
        float4 wv = w[m]; float4 xv = xs[m];
        acc += wv.x * xv.x + wv.y * xv.y + wv.z * xv.z + wv.w * xv.w;
    }
    acc = fmaxf(acc, 0.f);
    unsigned flat = blockIdx.x * PREN + j;
    g_dec_ins[flat] = drop_keep(k0, k1, flat) ? 2.f * acc : 0.f;
}

// ---------------------------- megakernel phases -----------------------------

// pre-loop: pmem = memory @ memory_w.T  (blocks 0..127: b=bid>>3, tc=bid&7)
__device__ void pmem_phase(float* smem_f, int bid,
                           const float* __restrict__ memory,
                           const float* __restrict__ memory_w) {
    float (*ms)[66] = (float (*)[66])smem_f;               // 32 x 66
    float (*ws)[66] = (float (*)[66])(smem_f + 32 * 66);   // 128 x 66
    int b = bid >> 3, tc = bid & 7, tid = threadIdx.x;
    int a = tid & 127, tg = tid >> 7;   // 4 groups x 8 t
    ull acc[8];
    #pragma unroll
    for (int i = 0; i < 8; i++) acc[i] = 0ull;
    for (int k0 = 0; k0 < ENCD; k0 += 64) {
        if (tid < 512) {
            int t = tid >> 4, kq = (tid & 15) << 2;
            float4 v = *(const float4*)(memory + ((size_t)(b * TENC) + tc * 32 + t) * ENCD + k0 + kq);
            float* d = &ms[t][kq];
            d[0] = v.x; d[1] = v.y; d[2] = v.z; d[3] = v.w;
        }
        for (int i4 = tid; i4 < 2048; i4 += NTHR) {
            int aa = i4 >> 4, kq = (i4 & 15) << 2;
            float4 v = *(const float4*)(memory_w + (size_t)aa * ENCD + k0 + kq);
            float* d = &ws[aa][kq];
            d[0] = v.x; d[1] = v.y; d[2] = v.z; d[3] = v.w;
        }
        __syncthreads();
        #pragma unroll 4
        for (int kp = 0; kp < 64; kp += 2) {
            ull wv = *(const ull*)&ws[a][kp];
            #pragma unroll
            for (int i = 0; i < 8; i++)
                acc[i] = ffma2(wv, *(const ull*)&ms[tg * 8 + i][kp], acc[i]);
        }
        __syncthreads();
    }
    #pragma unroll
    for (int i = 0; i < 8; i++) {
        float2 f = u2f(acc[i]);
        g_pmem[((size_t)(b * TENC) + tc * 32 + tg * 8 + i) * ADIMD + a] = f.x + f.y;
    }
}

// LSTM: blocks 0..127, 32 rows each. warp = 4 rows x 8 batches, lanes span k.
// Weights coalesced (512B/row-chunk per LDG.128); x via contiguous LDS.128.
template<int WHICH>
__device__ void lstm_phase(float* smem_f, int parity, int t,
                           const float* __restrict__ w_ih,
                           const float* __restrict__ w_hh,
                           const float* __restrict__ bias) {
    constexpr int IN1   = (WHICH == 0) ? PREN : ARNND;
    constexpr int INDIM = IN1 + ENCD;         // 768 / 1536
    constexpr int KTOT  = INDIM + 1024;       // 1792 / 2560
    constexpr int NJ    = KTOT / 128;         // 14 / 20
    constexpr int JIH   = INDIM / 128;        // 6 / 12
    const float *in1, *hin; float *hout, *cst;
    if (WHICH == 0) {
        in1 = g_dec_ins + (size_t)t * BB * PREN;
        hin = g_ah[parity]; hout = g_ah[parity ^ 1]; cst = g_ac;
    } else {
        in1 = g_ah[parity ^ 1];
        hin = g_dh[parity]; hout = g_dh[parity ^ 1]; cst = g_dc;
    }
    const float* in2 = g_actx;
    float* xs = smem_f;                        // [16][KTOT]
    float* sg = xs + 16 * KTOT;                // [32][16]
    int tid = threadIdx.x;

    // ---- stage x = [in1 | actx | hin] for all 16 batches (register-batched) ----
    constexpr int QTOT = 16 * (KTOT / 4);
    constexpr int QPT  = QTOT / NTHR;          // 14 / 20
    constexpr int CH   = (QPT % 5 == 0) ? 5 : 7;
    #pragma unroll
    for (int base = 0; base < QPT; base += CH) {
        float4 v[CH];
        #pragma unroll
        for (int i = 0; i < CH; i++) {
            int i4 = tid + (base + i) * NTHR;
            int b = i4 / (KTOT / 4);
            int k = (i4 - b * (KTOT / 4)) << 2;
            if (k < IN1)        v[i] = ldcg4(in1 + (size_t)b * IN1 + k);
            else if (k < INDIM) v[i] = ldcg4(in2 + (size_t)b * ENCD + (k - IN1));
            else                v[i] = ldcg4(hin + (size_t)b * 1024 + (k - INDIM));
        }
        #pragma unroll
        for (int i = 0; i < CH; i++) {
            int i4 = tid + (base + i) * NTHR;
            int b = i4 / (KTOT / 4);
            int k = (i4 - b * (KTOT / 4)) << 2;
            *(float4*)(xs + (size_t)b * KTOT + k) = v[i];
        }
    }
    __syncthreads();

    // ---- register-tiled GEMM ----
    int w = tid >> 5, lane = tid & 31;
    int rt = w & 7, bt = w >> 3;               // row-tile 0..7, batch-tile 0..1
    int grow[4];
    #pragma unroll
    for (int i = 0; i < 4; i++) {
        int rl = rt * 4 + i;
        grow[i] = ((rl >> 3) << 10) + (blockIdx.x << 3) + (rl & 7);
    }
    const float* xb = xs + (size_t)(bt * 8) * KTOT;
    ull acc[4][8];
    #pragma unroll
    for (int i = 0; i < 4; i++)
        #pragma unroll
        for (int b = 0; b < 8; b++) acc[i][b] = 0ull;

    for (int j = 0; j < NJ; j++) {
        int kb = j * 128 + (lane << 2);
        float4 wv[4];
        if (j < JIH) {
            #pragma unroll
            for (int i = 0; i < 4; i++)
                wv[i] = *(const float4*)(w_ih + (size_t)grow[i] * INDIM + kb);
        } else {
            #pragma unroll
            for (int i = 0; i < 4; i++)
                wv[i] = *(const float4*)(w_hh + (size_t)grow[i] * 1024 + (kb - INDIM));
        }
        #pragma unroll
        for (int h = 0; h < 2; h++) {
            float4 xv[4];
            #pragma unroll
            for (int bb = 0; bb < 4; bb++)
                xv[bb] = *(const float4*)(xb + (size_t)(h * 4 + bb) * KTOT + kb);
            #pragma unroll
            for (int i = 0; i < 4; i++) {
                ull w01 = *(const ull*)&wv[i].x;
                ull w23 = *(const ull*)&wv[i].z;
                #pragma unroll
                for (int bb = 0; bb < 4; bb++) {
                    int b = h * 4 + bb;
                    acc[i][b] = ffma2(w01, *(const ull*)&xv[bb].x, acc[i][b]);
                    acc[i][b] = ffma2(w23, *(const ull*)&xv[bb].z, acc[i][b]);
                }
            }
        }
    }
    // ---- lane reduction ----
    #pragma unroll
    for (int i = 0; i < 4; i++) {
        #pragma unroll
        for (int b = 0; b < 8; b++) {
            float2 f = u2f(acc[i][b]);
            float s = f.x + f.y;
            #pragma unroll
            for (int o = 16; o > 0; o >>= 1)
                s += __shfl_down_sync(0xffffffffu, s, o);
            if (lane == 0) sg[(rt * 4 + i) * 16 + bt * 8 + b] = s;
        }
    }
    __syncthreads();

    // ---- pointwise ----
    if (tid < 128) {
        int cl2 = tid >> 4, b2 = tid & 15;
        int rbase = (blockIdx.x << 3) + cl2;
        float gi = sg[cl2 * 16 + b2]        + bias[rbase];
        float gf = sg[(8 + cl2) * 16 + b2]  + bias[1024 + rbase];
        float gg = sg[(16 + cl2) * 16 + b2] + bias[2048 + rbase];
        float go = sg[(24 + cl2) * 16 + b2] + bias[3072 + rbase];
        int ci = b2 * 1024 + rbase;
        float cold = cst[ci];
        float si = 1.f / (1.f + expf(-gi));
        float sf = 1.f / (1.f + expf(-gf));
        float so = 1.f / (1.f + expf(-go));
        float cn = sf * cold + si * tanhf(gg);
        cst[ci] = cn;
        hout[ci] = so * tanhf(cn);
    }
}

// blocks 128..147: projection for step tprev (64 outputs/block, 8 thr each)
__device__ void proj_phase(int bid2, int parity, int tprev,
                           const float* __restrict__ proj_w,
                           const float* __restrict__ proj_b,
                           float* __restrict__ out) {
    int tid = threadIdx.x;
    int o = bid2 * 64 + (tid >> 3);
    int q8 = tid & 7;
    int b = o / NMELS, mel = o - b * NMELS;
    const float* dh = g_dh[parity] + (size_t)b * DECD;
    const float* ax = g_actx + (size_t)b * ENCD;
    const float* w = proj_w + (size_t)mel * (DECD + ENCD);
    ull acc = 0ull;
    int kst = q8 * 192;
    #pragma unroll 8
    for (int k = kst; k < kst + 192; k += 2) {
        ull wv = *(const ull*)(w + k);
        ull xv = (k < DECD) ? ldcg2u(dh + k) : ldcg2u(ax + (k - DECD));
        acc = ffma2(wv, xv, acc);
    }
    float2 f = u2f(acc);
    float s = f.x + f.y;
    s += __shfl_down_sync(0xffffffffu, s, 4, 8);
    s += __shfl_down_sync(0xffffffffu, s, 2, 8);
    s += __shfl_down_sync(0xffffffffu, s, 1, 8);
    if (q8 == 0)
        out[(size_t)b * (NMELS * TDEC) + mel * TDEC + tprev] = s + proj_b[mel];
}

// blocks 0..127: split query (16 dims each, coalesced) + location conv chunk.
__device__ void qconv_phase(float* smem_f, int bid, int parity,
                            const float* __restrict__ query_w,
                            const float* __restrict__ loc_conv_w) {
    float* ws0 = smem_f;            // 64
    float* ws1 = smem_f + 64;       // 64
    float* cw  = smem_f + 128;      // 64*31
    int b = bid >> 3, tc = bid & 7;
    int tid = threadIdx.x;

    if (tid < 62) {
        int tt = tc * 32 - PADC + tid;
        bool ok = (tt >= 0 && tt < TENC);
        ws0[tid] = ok ? ldcg1(g_aw + b * TENC + tt) : 0.f;
        ws1[tid] = ok ? ldcg1(g_awc + b * TENC + tt) : 0.f;
    }
    for (int i = tid; i < 64 * KCONV; i += NTHR) cw[i] = loc_conv_w[i];
    __syncthreads();

    // query: warp w -> dim a = (bid&7)*16 + w, lanes span k
    {
        int w = tid >> 5, lane = tid & 31;
        int a = tc * 16 + w;
        const float* wr = query_w + (size_t)a * ARNND;
        const float* ah = g_ah[parity ^ 1] + (size_t)b * ARNND;
        ull acc = 0ull;
        #pragma unroll
        for (int j = 0; j < 8; j++) {
            int kb = j * 128 + (lane << 2);
            float4 wv = *(const float4*)(wr + kb);
            float4 xv = ldcg4(ah + kb);
            acc = ffma2(*(const ull*)&wv.x, *(const ull*)&xv.x, acc);
            acc = ffma2(*(const ull*)&wv.z, *(const ull*)&xv.z, acc);
        }
        float2 f = u2f(acc);
        float s = f.x + f.y;
        #pragma unroll
        for (int o = 16; o > 0; o >>= 1)
            s += __shfl_down_sync(0xffffffffu, s, o);
        if (lane == 0) g_q[b * ADIMD + a] = s;
    }
    // conv: 32 t x 32 filters -> g_convf
    for (int i = tid; i < 1024; i += NTHR) {
        int tl = i >> 5, c = i & 31;
        const float* w0 = cw + c * 62;
        float s = 0.f;
        #pragma unroll
        for (int tap = 0; tap < KCONV; tap++)
            s += ws0[tl + tap] * w0[tap] + ws1[tl + tap] * w0[KCONV + tap];
        g_convf[((b << 8) + tc * 32 + tl) * NFILTD + c] = s;
    }
}

// blocks 0..127: energies for 32 t's
__device__ void energy_phase(float* smem_f, int bid,
                             const float* __restrict__ loc_dense_w,
                             const float* __restrict__ v_w) {
    float* sh_q   = smem_f;           // 128
    float* sh_ldt = smem_f + 128;     // 32*130
    float* sh_v   = sh_ldt + 4160;    // 128
    int b = bid >> 3, tc = bid & 7;
    int tid = threadIdx.x;
    if (tid < ADIMD) sh_q[tid] = ldcg1(g_q + b * ADIMD + tid);
    else if (tid < 2 * ADIMD) sh_v[tid - ADIMD] = v_w[tid - ADIMD];
    for (int i = tid; i < ADIMD * NFILTD; i += NTHR) {
        int a = i >> 5, c = i & 31;
        sh_ldt[c * 130 + a] = loc_dense_w[i];
    }
    __syncthreads();
    int wid = tid >> 5, lane = tid & 31;
    #pragma unroll
    for (int j = 0; j < 2; j++) {
        int tl = wid * 2 + j;
        int t = tc * 32 + tl;
        float fc_own = ldcg1(g_convf + ((size_t)(b << 8) + t) * NFILTD + lane);
        const float* pm = g_pmem + ((size_t)(b * TENC) + t) * ADIMD;
        float s0 = sh_q[lane]      + pm[lane];
        float s1 = sh_q[lane + 32] + pm[lane + 32];
        float s2 = sh_q[lane + 64] + pm[lane + 64];
        float s3 = sh_q[lane + 96] + pm[lane + 96];
        #pragma unroll
        for (int c = 0; c < NFILTD; c++) {
            float fc = __shfl_sync(0xffffffffu, fc_own, c);
            const float* lr = sh_ldt + c * 130;
            s0 += lr[lane] * fc;
            s1 += lr[lane + 32] * fc;
            s2 += lr[lane + 64] * fc;
            s3 += lr[lane + 96] * fc;
        }
        float e = tanhf(fminf(fmaxf(s0, -20.f), 20.f)) * sh_v[lane]
                + tanhf(fminf(fmaxf(s1, -20.f), 20.f)) * sh_v[lane + 32]
                + tanhf(fminf(fmaxf(s2, -20.f), 20.f)) * sh_v[lane + 64]
                + tanhf(fminf(fmaxf(s3, -20.f), 20.f)) * sh_v[lane + 96];
        #pragma unroll
        for (int o = 16; o > 0; o >>= 1) e += __shfl_down_sync(0xffffffffu, e, o);
        if (lane == 0) g_energy[b * TENC + t] = e;
    }
}

// blocks 0..127: softmax (+aw/awc by ec==0) and 64-wide context chunk
__device__ void ctx_phase(float* smem_f, int bid,
                          const int* __restrict__ lengths,
                          const float* __restrict__ memory) {
    float* red  = smem_f;            // 256
    float* saw  = red + 256;         // 256
    float* part = saw + 256;         // 512
    int b = bid >> 3, ec = bid & 7;
    int tid = threadIdx.x;
    int len = lengths[b];
    float e = 0.f, ex = 0.f;
    bool masked = true;
    if (tid < 256) {
        masked = (tid < len);                   // reference masks the PREFIX
        e = masked ? -FLT_MAX : ldcg1(g_energy + b * TENC + tid);
        red[tid] = e;
    }
    __syncthreads();
    for (int s = 128; s > 0; s >>= 1) {
        if (tid < s) red[tid] = fmaxf(red[tid], red[tid + s]);
        __syncthreads();
    }
    float m = red[0];
    __syncthreads();
    if (tid < 256) {
        ex = masked ? 0.f : expf(e - m);
        red[tid] = ex;
    }
    __syncthreads();
    for (int s = 128; s > 0; s >>= 1) {
        if (tid < s) red[tid] += red[tid + s];
        __syncthreads();
    }
    float inv = 1.f / red[0];
    if (tid < 256) {
        float aw = ex * inv;
        saw[tid] = aw;
        if (ec == 0) {
            g_aw[b * TENC + tid] = aw;
            g_awc[b * TENC + tid] += aw;
        }
    }
    __syncthreads();
    int e0 = (ec << 6) + (tid & 63), tq = tid >> 6;
    const float* mem = memory + (size_t)b * TENC * ENCD;
    float acc = 0.f;
    int ts = tq * 32;
    #pragma unroll 8
    for (int tt = ts; tt < ts + 32; tt++)
        acc += saw[tt] * mem[(size_t)tt * ENCD + e0];
    part[tid] = acc;
    __syncthreads();
    if (tid < 64) {
        float s = 0.f;
        #pragma unroll
        for (int q = 0; q < 8; q++) s += part[q * 64 + tid];
        g_actx[b * ENCD + (ec << 6) + tid] = s;
    }
}

// ------------------------------- megakernel ---------------------------------
__global__ __launch_bounds__(NTHR, 1)
void mega_kernel(const float* __restrict__ memory,
                 const int* __restrict__ lengths,
                 const float* __restrict__ memory_w,
                 const float* __restrict__ attn_w_ih,
                 const float* __restrict__ attn_w_hh,
                 const float* __restrict__ attn_b,
                 const float* __restrict__ dec_w_ih,
                 const float* __restrict__ dec_w_hh,
                 const float* __restrict__ dec_b,
                 const float* __restrict__ proj_w,
                 const float* __restrict__ proj_b,
                 const float* __restrict__ query_w,
                 const float* __restrict__ v_w,
                 const float* __restrict__ loc_conv_w,
                 const float* __restrict__ loc_dense_w,
                 float* __restrict__ out) {
    extern __shared__ __align__(16) float smem_f[];
    const int bid = blockIdx.x;
    // P: pmem
    if (bid < 128) pmem_phase(smem_f, bid, memory, memory_w);
    gsync();
    for (int t = 0; t < TDEC; t++) {
        const int parity = t & 1;
        // A: attn LSTM + proj(t-1)
        if (bid < 128) lstm_phase<0>(smem_f, parity, t, attn_w_ih, attn_w_hh, attn_b);
        else if (t > 0) proj_phase(bid - 128, parity, t - 1, proj_w, proj_b, out);
        gsync();
        // B: split query + conv
        if (bid < 128) qconv_phase(smem_f, bid, parity, query_w, loc_conv_w);
        gsync();
        // C: energy
        if (bid < 128) energy_phase(smem_f, bid, loc_dense_w, v_w);
        gsync();
        // D: softmax + context
        if (bid < 128) ctx_phase(smem_f, bid, lengths, memory);
        gsync();
        // E: decoder LSTM
        if (bid < 128) lstm_phase<1>(smem_f, parity, t, dec_w_ih, dec_w_hh, dec_b);
        gsync();
    }
    if (bid >= 128) proj_phase(bid - 128, TDEC & 1, TDEC - 1, proj_w, proj_b, out);
}

// --------------------------------- host -------------------------------------
extern "C" void kernel_launch(void* const* d_in, const int* in_sizes, int n_in,
                              void* d_out, int out_size) {
    (void)in_sizes; (void)n_in; (void)out_size;
    const float* memory     = (const float*)d_in[0];
    const float* dec_inputs = (const float*)d_in[1];
    const int*   lengths    = (const int*)d_in[2];
    const float* prenet_w1  = (const float*)d_in[3];
    const float* prenet_w2  = (const float*)d_in[4];
    const float* attn_w_ih  = (const float*)d_in[5];
    const float* attn_w_hh  = (const float*)d_in[6];
    const float* attn_b     = (const float*)d_in[7];
    const float* dec_w_ih   = (const float*)d_in[8];
    const float* dec_w_hh   = (const float*)d_in[9];
    const float* dec_b      = (const float*)d_in[10];
    const float* proj_w     = (const float*)d_in[11];
    const float* proj_b     = (const float*)d_in[12];
    const float* query_w    = (const float*)d_in[13];
    const float* memory_w   = (const float*)d_in[14];
    const float* v_w        = (const float*)d_in[15];
    const float* loc_conv_w = (const float*)d_in[16];
    const float* loc_dense_w= (const float*)d_in[17];
    float* out = (float*)d_out;

    unsigned dk0_0, dk0_1, dk1_0, dk1_1;
#if JAX_PARTITIONABLE
    threefry2x32(0u, 42u, 0u, 0u, dk0_0, dk0_1);
    threefry2x32(0u, 42u, 0u, 1u, dk1_0, dk1_1);
#else
    unsigned a0, a1, b0, b1;
    threefry2x32(0u, 42u, 0u, 2u, a0, a1);
    threefry2x32(0u, 42u, 1u, 3u, b0, b1);
    dk0_0 = a0; dk0_1 = b0; dk1_0 = a1; dk1_1 = b1;
#endif

    const int SMEM_MEGA = (16 * 2560 + 512) * (int)sizeof(float);   // 165888
    static int configured = 0;
    if (!configured) {
        cudaFuncSetAttribute(mega_kernel,
                             cudaFuncAttributeMaxDynamicSharedMemorySize, SMEM_MEGA);
        configured = 1;
    }

    init_kernel<<<64, 256>>>();
    prenet1_kernel<<<(TDEC + 1) * BB, 256>>>(dec_inputs, prenet_w1, dk0_0, dk0_1);
    prenet2_kernel<<<(TDEC + 1) * BB, 256>>>(prenet_w2, dk1_0, dk1_1);
    mega_kernel<<<NBLK, NTHR, SMEM_MEGA>>>(memory, lengths, memory_w,
                                           attn_w_ih, attn_w_hh, attn_b,
                                           dec_w_ih, dec_w_hh, dec_b,
                                           proj_w, proj_b, query_w, v_w,
                                           loc_conv_w, loc_dense_w, out);
}

// round 17
// speedup vs baseline: 1.4771x; 1.0050x over previous
#include <cuda_runtime.h>
#include <math.h>
#include <float.h>

#define JAX_PARTITIONABLE 1

#define BB     16
#define TENC   256
#define TDEC   200
#define NMELS  80
#define PREN   256
#define ENCD   512
#define DECD   1024
#define ARNND  1024
#define ADIMD  128
#define NFILTD 32
#define KCONV  31
#define PADC   15
#define NBLK   296
#define NTHR   512

typedef unsigned long long ull;

// ------------------- scratch (device globals; no allocation) ----------------
__device__ float g_y1[(TDEC + 1) * BB * PREN];
__device__ float g_dec_ins[(TDEC + 1) * BB * PREN];
__device__ float g_pmem[BB * TENC * ADIMD];
__device__ float g_ah[2][BB * ARNND];
__device__ float g_ac[BB * ARNND];
__device__ float g_dh[2][BB * DECD];
__device__ float g_dc[BB * DECD];
__device__ float g_aw[BB * TENC];
__device__ float g_awc[BB * TENC];
__device__ float g_actx[BB * ENCD];
__device__ float g_q[BB * ADIMD];
__device__ float g_energy[BB * TENC];
__device__ float g_convf[BB * TENC * NFILTD];

__device__ unsigned g_bar_cnt = 0;
__device__ unsigned g_bar_epoch = 0;

// ----------------------------- grid barrier ---------------------------------
__device__ __forceinline__ void gsync() {
    __syncthreads();
    if (threadIdx.x == 0) {
        volatile unsigned* ep = &g_bar_epoch;
        unsigned e = *ep;
        __threadfence();
        unsigned old = atomicAdd(&g_bar_cnt, 1u);
        if (old == (unsigned)(NBLK - 1)) {
            g_bar_cnt = 0;
            __threadfence();
            *ep = e + 1u;
        } else {
            while (*ep == e) { __nanosleep(20); }
            __threadfence();
        }
    }
    __syncthreads();
}

// ------------------------------ packed f32x2 fma ----------------------------
__device__ __forceinline__ ull ffma2(ull a, ull b, ull c) {
    ull d;
    asm("fma.rn.f32x2 %0, %1, %2, %3;" : "=l"(d) : "l"(a), "l"(b), "l"(c));
    return d;
}
__device__ __forceinline__ float2 u2f(ull v) {
    float2 f;
    asm("mov.b64 {%0, %1}, %2;" : "=f"(f.x), "=f"(f.y) : "l"(v));
    return f;
}

// ----------------------------- L1-bypassing loads ---------------------------
__device__ __forceinline__ float4 ldcg4(const float* p) {
    float4 v;
    asm volatile("ld.global.cg.v4.f32 {%0,%1,%2,%3}, [%4];"
                 : "=f"(v.x), "=f"(v.y), "=f"(v.z), "=f"(v.w) : "l"(p));
    return v;
}
__device__ __forceinline__ ull ldcg2u(const float* p) {
    ull v;
    asm volatile("ld.global.cg.b64 %0, [%1];" : "=l"(v) : "l"(p));
    return v;
}
__device__ __forceinline__ float ldcg1(const float* p) {
    float v;
    asm volatile("ld.global.cg.f32 %0, [%1];" : "=f"(v) : "l"(p));
    return v;
}

// ------------------------------- threefry ----------------------------------
__host__ __device__ inline void threefry2x32(unsigned k0, unsigned k1,
                                             unsigned x0, unsigned x1,
                                             unsigned& o0, unsigned& o1) {
    unsigned ks2 = k0 ^ k1 ^ 0x1BD11BDAu;
    x0 += k0; x1 += k1;
#define TFR(d) { x0 += x1; x1 = (x1 << (d)) | (x1 >> (32 - (d))); x1 ^= x0; }
    TFR(13) TFR(15) TFR(26) TFR(6)
    x0 += k1;  x1 += ks2 + 1u;
    TFR(17) TFR(29) TFR(16) TFR(24)
    x0 += ks2; x1 += k0 + 2u;
    TFR(13) TFR(15) TFR(26) TFR(6)
    x0 += k0;  x1 += k1 + 3u;
    TFR(17) TFR(29) TFR(16) TFR(24)
    x0 += k1;  x1 += ks2 + 4u;
    TFR(13) TFR(15) TFR(26) TFR(6)
    x0 += ks2; x1 += k0 + 5u;
#undef TFR
    o0 = x0; o1 = x1;
}

__device__ inline bool drop_keep(unsigned k0, unsigned k1, unsigned i) {
#if JAX_PARTITIONABLE
    unsigned o0, o1;
    threefry2x32(k0, k1, 0u, i, o0, o1);
    unsigned bits = o0 ^ o1;
#else
    const unsigned half = ((TDEC + 1) * BB * PREN) / 2u;
    unsigned lo = (i < half) ? i : (i - half);
    unsigned o0, o1;
    threefry2x32(k0, k1, lo, lo + half, o0, o1);
    unsigned bits = (i < half) ? o0 : o1;
#endif
    return (bits >> 31) == 0u;
}

// ------------------------------ prologue ------------------------------------
__global__ void init_kernel() {
    int i = blockIdx.x * blockDim.x + threadIdx.x;
    if (i < BB * ARNND) { g_ah[0][i] = 0.f; g_ac[i] = 0.f; g_dh[0][i] = 0.f; g_dc[i] = 0.f; }
    if (i < BB * TENC)  { g_aw[i] = 0.f; g_awc[i] = 0.f; }
    if (i < BB * ENCD)  { g_actx[i] = 0.f; }
}

__global__ void prenet1_kernel(const float* __restrict__ dec_inputs,
                               const float* __restrict__ w1,
                               unsigned k0, unsigned k1) {
    __shared__ float xr[NMELS];
    int t = blockIdx.x / BB, b = blockIdx.x % BB;
    int j = threadIdx.x;
    if (j < NMELS) xr[j] = (t == 0) ? 0.f : dec_inputs[(b * NMELS + j) * TDEC + (t - 1)];
    __syncthreads();
    float acc = 0.f;
    const float* w = w1 + j * NMELS;
    #pragma unroll
    for (int m = 0; m < NMELS; m++) acc += xr[m] * w[m];
    acc = fmaxf(acc, 0.f);
    unsigned flat = blockIdx.x * PREN + j;
    g_y1[flat] = drop_keep(k0, k1, flat) ? 2.f * acc : 0.f;
}

__global__ void prenet2_kernel(const float* __restrict__ w2,
                               unsigned k0, unsigned k1) {
    __shared__ float xr[PREN];
    int j = threadIdx.x;
    xr[j] = g_y1[blockIdx.x * PREN + j];
    __syncthreads();
    float acc = 0.f;
    const float4* w = (const float4*)(w2 + (size_t)j * PREN);
    const float4* xs = (const float4*)xr;
    #pragma unroll 8
    for (int m = 0; m < PREN / 4; m++) {
        float4 wv = w[m]; float4 xv = xs[m];
        acc += wv.x * xv.x + wv.y * xv.y + wv.z * xv.z + wv.w * xv.w;
    }
    acc = fmaxf(acc, 0.f);
    unsigned flat = blockIdx.x * PREN + j;
    g_dec_ins[flat] = drop_keep(k0, k1, flat) ? 2.f * acc : 0.f;
}

// ---------------------------- megakernel phases -----------------------------

// pre-loop: pmem = memory @ memory_w.T  (blocks 0..127: b=bid>>3, tc=bid&7)
__device__ void pmem_phase(float* smem_f, int bid,
                           const float* __restrict__ memory,
                           const float* __restrict__ memory_w) {
    float (*ms)[66] = (float (*)[66])smem_f;               // 32 x 66
    float (*ws)[66] = (float (*)[66])(smem_f + 32 * 66);   // 128 x 66
    int b = bid >> 3, tc = bid & 7, tid = threadIdx.x;
    int a = tid & 127, tg = tid >> 7;   // 4 groups x 8 t
    ull acc[8];
    #pragma unroll
    for (int i = 0; i < 8; i++) acc[i] = 0ull;
    for (int k0 = 0; k0 < ENCD; k0 += 64) {
        if (tid < 512) {
            int t = tid >> 4, kq = (tid & 15) << 2;
            float4 v = *(const float4*)(memory + ((size_t)(b * TENC) + tc * 32 + t) * ENCD + k0 + kq);
            float* d = &ms[t][kq];
            d[0] = v.x; d[1] = v.y; d[2] = v.z; d[3] = v.w;
        }
        for (int i4 = tid; i4 < 2048; i4 += NTHR) {
            int aa = i4 >> 4, kq = (i4 & 15) << 2;
            float4 v = *(const float4*)(memory_w + (size_t)aa * ENCD + k0 + kq);
            float* d = &ws[aa][kq];
            d[0] = v.x; d[1] = v.y; d[2] = v.z; d[3] = v.w;
        }
        __syncthreads();
        #pragma unroll 4
        for (int kp = 0; kp < 64; kp += 2) {
            ull wv = *(const ull*)&ws[a][kp];
            #pragma unroll
            for (int i = 0; i < 8; i++)
                acc[i] = ffma2(wv, *(const ull*)&ms[tg * 8 + i][kp], acc[i]);
        }
        __syncthreads();
    }
    #pragma unroll
    for (int i = 0; i < 8; i++) {
        float2 f = u2f(acc[i]);
        g_pmem[((size_t)(b * TENC) + tc * 32 + tg * 8 + i) * ADIMD + a] = f.x + f.y;
    }
}

// LSTM: blocks 0..255. block = (rowblk = bid>>1 : 32 rows, bhalf = bid&1 : 8 batches)
// warp = 4 rows x 4 batches, lanes span k (coalesced 512B weight rows).
template<int WHICH>
__device__ void lstm_phase(float* smem_f, int bid, int parity, int t,
                           const float* __restrict__ w_ih,
                           const float* __restrict__ w_hh,
                           const float* __restrict__ bias) {
    constexpr int IN1   = (WHICH == 0) ? PREN : ARNND;
    constexpr int INDIM = IN1 + ENCD;         // 768 / 1536
    constexpr int KTOT  = INDIM + 1024;       // 1792 / 2560
    constexpr int NJ    = KTOT / 128;         // 14 / 20
    constexpr int JIH   = INDIM / 128;        // 6 / 12
    const float *in1, *hin; float *hout, *cst;
    if (WHICH == 0) {
        in1 = g_dec_ins + (size_t)t * BB * PREN;
        hin = g_ah[parity]; hout = g_ah[parity ^ 1]; cst = g_ac;
    } else {
        in1 = g_ah[parity ^ 1];
        hin = g_dh[parity]; hout = g_dh[parity ^ 1]; cst = g_dc;
    }
    const float* in2 = g_actx;
    int rowblk = bid >> 1, bhalf = bid & 1;
    float* xs = smem_f;                        // [8][KTOT]
    float* sg = xs + 8 * KTOT;                 // [32][8]
    int tid = threadIdx.x;

    // ---- stage x = [in1 | actx | hin] for this block's 8 batches ----
    constexpr int QUADS = KTOT / 4;
    for (int i4 = tid; i4 < 8 * QUADS; i4 += NTHR) {
        int b = i4 / QUADS;
        int k = (i4 - b * QUADS) << 2;
        int gb = bhalf * 8 + b;
        float4 v;
        if (k < IN1)        v = ldcg4(in1 + (size_t)gb * IN1 + k);
        else if (k < INDIM) v = ldcg4(in2 + (size_t)gb * ENCD + (k - IN1));
        else                v = ldcg4(hin + (size_t)gb * 1024 + (k - INDIM));
        *(float4*)(xs + (size_t)b * KTOT + k) = v;
    }
    __syncthreads();

    // ---- register-tiled GEMM: warp = 4 rows x 4 batches ----
    int w = tid >> 5, lane = tid & 31;
    int rt = w & 7, bt = w >> 3;               // 8 row-tiles x 2 batch-tiles
    int grow[4];
    #pragma unroll
    for (int i = 0; i < 4; i++) {
        int rl = rt * 4 + i;
        grow[i] = ((rl >> 3) << 10) + (rowblk << 3) + (rl & 7);
    }
    const float* xb = xs + (size_t)(bt * 4) * KTOT;
    ull acc[4][4];
    #pragma unroll
    for (int i = 0; i < 4; i++)
        #pragma unroll
        for (int b = 0; b < 4; b++) acc[i][b] = 0ull;

    for (int j = 0; j < NJ; j++) {
        int kb = j * 128 + (lane << 2);
        const float* wbase;
        size_t wstride;
        int kw;
        if (j < JIH) { wbase = w_ih; wstride = INDIM; kw = kb; }
        else         { wbase = w_hh; wstride = 1024;  kw = kb - INDIM; }
        // rows 0,1
        {
            float4 wv0 = *(const float4*)(wbase + (size_t)grow[0] * wstride + kw);
            float4 wv1 = *(const float4*)(wbase + (size_t)grow[1] * wstride + kw);
            ull w0a = *(const ull*)&wv0.x, w0b = *(const ull*)&wv0.z;
            ull w1a = *(const ull*)&wv1.x, w1b = *(const ull*)&wv1.z;
            #pragma unroll
            for (int bb = 0; bb < 4; bb++) {
                float4 xv = *(const float4*)(xb + (size_t)bb * KTOT + kb);
                ull xa = *(const ull*)&xv.x, xc = *(const ull*)&xv.z;
                acc[0][bb] = ffma2(w0a, xa, acc[0][bb]);
                acc[0][bb] = ffma2(w0b, xc, acc[0][bb]);
                acc[1][bb] = ffma2(w1a, xa, acc[1][bb]);
                acc[1][bb] = ffma2(w1b, xc, acc[1][bb]);
            }
        }
        // rows 2,3
        {
            float4 wv2 = *(const float4*)(wbase + (size_t)grow[2] * wstride + kw);
            float4 wv3 = *(const float4*)(wbase + (size_t)grow[3] * wstride + kw);
            ull w2a = *(const ull*)&wv2.x, w2b = *(const ull*)&wv2.z;
            ull w3a = *(const ull*)&wv3.x, w3b = *(const ull*)&wv3.z;
            #pragma unroll
            for (int bb = 0; bb < 4; bb++) {
                float4 xv = *(const float4*)(xb + (size_t)bb * KTOT + kb);
                ull xa = *(const ull*)&xv.x, xc = *(const ull*)&xv.z;
                acc[2][bb] = ffma2(w2a, xa, acc[2][bb]);
                acc[2][bb] = ffma2(w2b, xc, acc[2][bb]);
                acc[3][bb] = ffma2(w3a, xa, acc[3][bb]);
                acc[3][bb] = ffma2(w3b, xc, acc[3][bb]);
            }
        }
    }
    // ---- lane reduction ----
    #pragma unroll
    for (int i = 0; i < 4; i++) {
        #pragma unroll
        for (int b = 0; b < 4; b++) {
            float2 f = u2f(acc[i][b]);
            float s = f.x + f.y;
            #pragma unroll
            for (int o = 16; o > 0; o >>= 1)
                s += __shfl_down_sync(0xffffffffu, s, o);
            if (lane == 0) sg[(rt * 4 + i) * 8 + bt * 4 + b] = s;
        }
    }
    __syncthreads();

    // ---- pointwise: 8 cells x 8 batches ----
    if (tid < 64) {
        int cl2 = tid >> 3, b2l = tid & 7;
        int rbase = (rowblk << 3) + cl2;
        float gi = sg[cl2 * 8 + b2l]        + bias[rbase];
        float gf = sg[(8 + cl2) * 8 + b2l]  + bias[1024 + rbase];
        float gg = sg[(16 + cl2) * 8 + b2l] + bias[2048 + rbase];
        float go = sg[(24 + cl2) * 8 + b2l] + bias[3072 + rbase];
        int gb = bhalf * 8 + b2l;
        int ci = gb * 1024 + rbase;
        float cold = cst[ci];
        float si = 1.f / (1.f + expf(-gi));
        float sf = 1.f / (1.f + expf(-gf));
        float so = 1.f / (1.f + expf(-go));
        float cn = sf * cold + si * tanhf(gg);
        cst[ci] = cn;
        hout[ci] = so * tanhf(cn);
    }
}

// blocks 256..295: projection for step tprev (32 outputs/block, 16 thr each)
__device__ void proj_phase(int bid2, int parity, int tprev,
                           const float* __restrict__ proj_w,
                           const float* __restrict__ proj_b,
                           float* __restrict__ out) {
    int tid = threadIdx.x;
    int o = bid2 * 32 + (tid >> 4);            // 0..1279
    int q16 = tid & 15;
    int b = o / NMELS, mel = o - b * NMELS;
    const float* dh = g_dh[parity] + (size_t)b * DECD;
    const float* ax = g_actx + (size_t)b * ENCD;
    const float* w = proj_w + (size_t)mel * (DECD + ENCD);
    ull acc = 0ull;
    int kst = q16 * 96;
    #pragma unroll 8
    for (int k = kst; k < kst + 96; k += 2) {
        ull wv = *(const ull*)(w + k);
        ull xv = (k < DECD) ? ldcg2u(dh + k) : ldcg2u(ax + (k - DECD));
        acc = ffma2(wv, xv, acc);
    }
    float2 f = u2f(acc);
    float s = f.x + f.y;
    s += __shfl_down_sync(0xffffffffu, s, 8, 16);
    s += __shfl_down_sync(0xffffffffu, s, 4, 16);
    s += __shfl_down_sync(0xffffffffu, s, 2, 16);
    s += __shfl_down_sync(0xffffffffu, s, 1, 16);
    if (q16 == 0)
        out[(size_t)b * (NMELS * TDEC) + mel * TDEC + tprev] = s + proj_b[mel];
}

// blocks 0..127: split query (16 dims each, coalesced)
__device__ void query_phase(int bid, int parity,
                            const float* __restrict__ query_w) {
    int b = bid >> 3, tc = bid & 7;
    int tid = threadIdx.x;
    int w = tid >> 5, lane = tid & 31;
    int a = tc * 16 + w;
    const float* wr = query_w + (size_t)a * ARNND;
    const float* ah = g_ah[parity ^ 1] + (size_t)b * ARNND;
    ull acc = 0ull;
    #pragma unroll
    for (int j = 0; j < 8; j++) {
        int kb = j * 128 + (lane << 2);
        float4 wv = *(const float4*)(wr + kb);
        float4 xv = ldcg4(ah + kb);
        acc = ffma2(*(const ull*)&wv.x, *(const ull*)&xv.x, acc);
        acc = ffma2(*(const ull*)&wv.z, *(const ull*)&xv.z, acc);
    }
    float2 f = u2f(acc);
    float s = f.x + f.y;
    #pragma unroll
    for (int o = 16; o > 0; o >>= 1)
        s += __shfl_down_sync(0xffffffffu, s, o);
    if (lane == 0) g_q[b * ADIMD + a] = s;
}

// blocks 128..255: location conv chunk -> g_convf
__device__ void conv_phase(float* smem_f, int task,
                           const float* __restrict__ loc_conv_w) {
    float* ws0 = smem_f;            // 64
    float* ws1 = smem_f + 64;       // 64
    float* cw  = smem_f + 128;      // 64*31
    int b = task >> 3, tc = task & 7;
    int tid = threadIdx.x;
    if (tid < 62) {
        int tt = tc * 32 - PADC + tid;
        bool ok = (tt >= 0 && tt < TENC);
        ws0[tid] = ok ? ldcg1(g_aw + b * TENC + tt) : 0.f;
        ws1[tid] = ok ? ldcg1(g_awc + b * TENC + tt) : 0.f;
    }
    for (int i = tid; i < 64 * KCONV; i += NTHR) cw[i] = loc_conv_w[i];
    __syncthreads();
    for (int i = tid; i < 1024; i += NTHR) {
        int tl = i >> 5, c = i & 31;
        const float* w0 = cw + c * 62;
        float s = 0.f;
        #pragma unroll
        for (int tap = 0; tap < KCONV; tap++)
            s += ws0[tl + tap] * w0[tap] + ws1[tl + tap] * w0[KCONV + tap];
        g_convf[((b << 8) + tc * 32 + tl) * NFILTD + c] = s;
    }
}

// blocks 0..127: energies for 32 t's
__device__ void energy_phase(float* smem_f, int bid,
                             const float* __restrict__ loc_dense_w,
                             const float* __restrict__ v_w) {
    float* sh_q   = smem_f;           // 128
    float* sh_ldt = smem_f + 128;     // 32*130
    float* sh_v   = sh_ldt + 4160;    // 128
    int b = bid >> 3, tc = bid & 7;
    int tid = threadIdx.x;
    if (tid < ADIMD) sh_q[tid] = ldcg1(g_q + b * ADIMD + tid);
    else if (tid < 2 * ADIMD) sh_v[tid - ADIMD] = v_w[tid - ADIMD];
    for (int i = tid; i < ADIMD * NFILTD; i += NTHR) {
        int a = i >> 5, c = i & 31;
        sh_ldt[c * 130 + a] = loc_dense_w[i];
    }
    __syncthreads();
    int wid = tid >> 5, lane = tid & 31;
    #pragma unroll
    for (int j = 0; j < 2; j++) {
        int tl = wid * 2 + j;
        int t = tc * 32 + tl;
        float fc_own = ldcg1(g_convf + ((size_t)(b << 8) + t) * NFILTD + lane);
        const float* pm = g_pmem + ((size_t)(b * TENC) + t) * ADIMD;
        float s0 = sh_q[lane]      + pm[lane];
        float s1 = sh_q[lane + 32] + pm[lane + 32];
        float s2 = sh_q[lane + 64] + pm[lane + 64];
        float s3 = sh_q[lane + 96] + pm[lane + 96];
        #pragma unroll
        for (int c = 0; c < NFILTD; c++) {
            float fc = __shfl_sync(0xffffffffu, fc_own, c);
            const float* lr = sh_ldt + c * 130;
            s0 += lr[lane] * fc;
            s1 += lr[lane + 32] * fc;
            s2 += lr[lane + 64] * fc;
            s3 += lr[lane + 96] * fc;
        }
        float e = tanhf(fminf(fmaxf(s0, -20.f), 20.f)) * sh_v[lane]
                + tanhf(fminf(fmaxf(s1, -20.f), 20.f)) * sh_v[lane + 32]
                + tanhf(fminf(fmaxf(s2, -20.f), 20.f)) * sh_v[lane + 64]
                + tanhf(fminf(fmaxf(s3, -20.f), 20.f)) * sh_v[lane + 96];
        #pragma unroll
        for (int o = 16; o > 0; o >>= 1) e += __shfl_down_sync(0xffffffffu, e, o);
        if (lane == 0) g_energy[b * TENC + t] = e;
    }
}

// blocks 0..127: softmax (+aw/awc by ec==0) and 64-wide context chunk
__device__ void ctx_phase(float* smem_f, int bid,
                          const int* __restrict__ lengths,
                          const float* __restrict__ memory) {
    float* red  = smem_f;            // 256
    float* saw  = red + 256;         // 256
    float* part = saw + 256;         // 512
    int b = bid >> 3, ec = bid & 7;
    int tid = threadIdx.x;
    int len = lengths[b];
    float e = 0.f, ex = 0.f;
    bool masked = true;
    if (tid < 256) {
        masked = (tid < len);                   // reference masks the PREFIX
        e = masked ? -FLT_MAX : ldcg1(g_energy + b * TENC + tid);
        red[tid] = e;
    }
    __syncthreads();
    for (int s = 128; s > 0; s >>= 1) {
        if (tid < s) red[tid] = fmaxf(red[tid], red[tid + s]);
        __syncthreads();
    }
    float m = red[0];
    __syncthreads();
    if (tid < 256) {
        ex = masked ? 0.f : expf(e - m);
        red[tid] = ex;
    }
    __syncthreads();
    for (int s = 128; s > 0; s >>= 1) {
        if (tid < s) red[tid] += red[tid + s];
        __syncthreads();
    }
    float inv = 1.f / red[0];
    if (tid < 256) {
        float aw = ex * inv;
        saw[tid] = aw;
        if (ec == 0) {
            g_aw[b * TENC + tid] = aw;
            g_awc[b * TENC + tid] += aw;
        }
    }
    __syncthreads();
    int e0 = (ec << 6) + (tid & 63), tq = tid >> 6;
    const float* mem = memory + (size_t)b * TENC * ENCD;
    float acc = 0.f;
    int ts = tq * 32;
    #pragma unroll 8
    for (int tt = ts; tt < ts + 32; tt++)
        acc += saw[tt] * mem[(size_t)tt * ENCD + e0];
    part[tid] = acc;
    __syncthreads();
    if (tid < 64) {
        float s = 0.f;
        #pragma unroll
        for (int q = 0; q < 8; q++) s += part[q * 64 + tid];
        g_actx[b * ENCD + (ec << 6) + tid] = s;
    }
}

// ------------------------------- megakernel ---------------------------------
__global__ __launch_bounds__(NTHR, 2)
void mega_kernel(const float* __restrict__ memory,
                 const int* __restrict__ lengths,
                 const float* __restrict__ memory_w,
                 const float* __restrict__ attn_w_ih,
                 const float* __restrict__ attn_w_hh,
                 const float* __restrict__ attn_b,
                 const float* __restrict__ dec_w_ih,
                 const float* __restrict__ dec_w_hh,
                 const float* __restrict__ dec_b,
                 const float* __restrict__ proj_w,
                 const float* __restrict__ proj_b,
                 const float* __restrict__ query_w,
                 const float* __restrict__ v_w,
                 const float* __restrict__ loc_conv_w,
                 const float* __restrict__ loc_dense_w,
                 float* __restrict__ out) {
    extern __shared__ __align__(16) float smem_f[];
    const int bid = blockIdx.x;
    // P: pmem
    if (bid < 128) pmem_phase(smem_f, bid, memory, memory_w);
    gsync();
    for (int t = 0; t < TDEC; t++) {
        const int parity = t & 1;
        // A: attn LSTM (0..255) + proj(t-1) (256..295)
        if (bid < 256) lstm_phase<0>(smem_f, bid, parity, t, attn_w_ih, attn_w_hh, attn_b);
        else if (t > 0) proj_phase(bid - 256, parity, t - 1, proj_w, proj_b, out);
        gsync();
        // B: query (0..127) || conv (128..255)
        if (bid < 128) query_phase(bid, parity, query_w);
        else if (bid < 256) conv_phase(smem_f, bid - 128, loc_conv_w);
        gsync();
        // C: energy
        if (bid < 128) energy_phase(smem_f, bid, loc_dense_w, v_w);
        gsync();
        // D: softmax + context
        if (bid < 128) ctx_phase(smem_f, bid, lengths, memory);
        gsync();
        // E: decoder LSTM
        if (bid < 256) lstm_phase<1>(smem_f, bid, parity, t, dec_w_ih, dec_w_hh, dec_b);
        gsync();
    }
    if (bid >= 256) proj_phase(bid - 256, TDEC & 1, TDEC - 1, proj_w, proj_b, out);
}

// --------------------------------- host -------------------------------------
extern "C" void kernel_launch(void* const* d_in, const int* in_sizes, int n_in,
                              void* d_out, int out_size) {
    (void)in_sizes; (void)n_in; (void)out_size;
    const float* memory     = (const float*)d_in[0];
    const float* dec_inputs = (const float*)d_in[1];
    const int*   lengths    = (const int*)d_in[2];
    const float* prenet_w1  = (const float*)d_in[3];
    const float* prenet_w2  = (const float*)d_in[4];
    const float* attn_w_ih  = (const float*)d_in[5];
    const float* attn_w_hh  = (const float*)d_in[6];
    const float* attn_b     = (const float*)d_in[7];
    const float* dec_w_ih   = (const float*)d_in[8];
    const float* dec_w_hh   = (const float*)d_in[9];
    const float* dec_b      = (const float*)d_in[10];
    const float* proj_w     = (const float*)d_in[11];
    const float* proj_b     = (const float*)d_in[12];
    const float* query_w    = (const float*)d_in[13];
    const float* memory_w   = (const float*)d_in[14];
    const float* v_w        = (const float*)d_in[15];
    const float* loc_conv_w = (const float*)d_in[16];
    const float* loc_dense_w= (const float*)d_in[17];
    float* out = (float*)d_out;

    unsigned dk0_0, dk0_1, dk1_0, dk1_1;
#if JAX_PARTITIONABLE
    threefry2x32(0u, 42u, 0u, 0u, dk0_0, dk0_1);
    threefry2x32(0u, 42u, 0u, 1u, dk1_0, dk1_1);
#else
    unsigned a0, a1, b0, b1;
    threefry2x32(0u, 42u, 0u, 2u, a0, a1);
    threefry2x32(0u, 42u, 1u, 3u, b0, b1);
    dk0_0 = a0; dk0_1 = b0; dk1_0 = a1; dk1_1 = b1;
#endif

    // per block: x-staging 8*2560 floats + 256 gate floats = 82944 B (2 blocks/SM)
    const int SMEM_MEGA = (8 * 2560 + 256) * (int)sizeof(float);
    static int configured = 0;
    if (!configured) {
        cudaFuncSetAttribute(mega_kernel,
                             cudaFuncAttributeMaxDynamicSharedMemorySize, SMEM_MEGA);
        configured = 1;
    }

    init_kernel<<<64, 256>>>();
    prenet1_kernel<<<(TDEC + 1) * BB, 256>>>(dec_inputs, prenet_w1, dk0_0, dk0_1);
    prenet2_kernel<<<(TDEC + 1) * BB, 256>>>(prenet_w2, dk1_0, dk1_1);
    mega_kernel<<<NBLK, NTHR, SMEM_MEGA>>>(memory, lengths, memory_w,
                                           attn_w_ih, attn_w_hh, attn_b,
                                           dec_w_ih, dec_w_hh, dec_b,
                                           proj_w, proj_b, query_w, v_w,
                                           loc_conv_w, loc_dense_w, out);
}